// round 10
// baseline (speedup 1.0000x reference)
#include <cuda_runtime.h>
#include <cuda_bf16.h>
#include <math.h>
#include <stdint.h>

// Problem constants
#define S     2048
#define HID   2048
#define NH    16
#define HD    128
#define BS_   64
#define NQB   32
#define NKB   32
#define KSEL  511
#define SCALE 0.08838834764831845f

// ---------------- device scratch (allocation-free) ----------------
__device__ float g_Vblk[NH * NKB * HD];
__device__ float g_Vtot[NH * HD];
__device__ int   g_list[NH * NQB * NKB];
__device__ int   g_cnt[NH * NQB];

// split-bf16 operands
__device__ __nv_bfloat16 g_Xhi[S * HID], g_Xlo[S * HID];
__device__ __nv_bfloat16 g_WThi[4][HID * HID], g_WTlo[4][HID * HID];  // [N,K]
__device__ __nv_bfloat16 g_AThi[S * HID], g_ATlo[S * HID];            // attn out, split

// attention operands (produced by GEMM epilogues)
__device__ __nv_bfloat16 g_Qhi[NH * S * HD], g_Qlo[NH * S * HD];   // [h][s][d], RoPE'd
__device__ __nv_bfloat16 g_Khi[NH * S * HD], g_Klo[NH * S * HD];   // [h][s][d], RoPE'd
__device__ __nv_bfloat16 g_Vthi[NH * HD * S], g_Vtlo[NH * HD * S]; // [h][d][s] transposed

// ---------------- helpers ----------------
__device__ __forceinline__ uint32_t smem_u32(const void* p) {
    uint32_t a;
    asm("{ .reg .u64 t; cvta.to.shared.u64 t, %1; cvt.u32.u64 %0, t; }" : "=r"(a) : "l"(p));
    return a;
}
__device__ __forceinline__ void ldsm4(uint32_t (&r)[4], uint32_t addr) {
    asm volatile("ldmatrix.sync.aligned.m8n8.x4.shared.b16 {%0,%1,%2,%3}, [%4];"
        : "=r"(r[0]), "=r"(r[1]), "=r"(r[2]), "=r"(r[3]) : "r"(addr));
}
__device__ __forceinline__ void mma_bf16(float (&d)[4], const uint32_t (&a)[4],
                                         uint32_t b0, uint32_t b1) {
    asm volatile("mma.sync.aligned.m16n8k16.row.col.f32.bf16.bf16.f32 "
        "{%0,%1,%2,%3}, {%4,%5,%6,%7}, {%8,%9}, {%0,%1,%2,%3};"
        : "+f"(d[0]), "+f"(d[1]), "+f"(d[2]), "+f"(d[3])
        : "r"(a[0]), "r"(a[1]), "r"(a[2]), "r"(a[3]), "r"(b0), "r"(b1));
}
#define CP_ASYNC16(dst, src) \
    asm volatile("cp.async.cg.shared.global [%0], [%1], 16;" :: "r"(dst), "l"(src))
#define CP_COMMIT() asm volatile("cp.async.commit_group;" ::: "memory")

__device__ __forceinline__ void split2(float a, float b, uint32_t& hi, uint32_t& lo) {
    __nv_bfloat16 ah = __float2bfloat16(a), bh = __float2bfloat16(b);
    float al = a - __bfloat162float(ah), bl = b - __bfloat162float(bh);
    __nv_bfloat16 alh = __float2bfloat16(al), blh = __float2bfloat16(bl);
    hi = ((uint32_t)__bfloat16_as_ushort(bh) << 16) | __bfloat16_as_ushort(ah);
    lo = ((uint32_t)__bfloat16_as_ushort(blh) << 16) | __bfloat16_as_ushort(alh);
}

// ---------------- fp32 -> bf16 hi/lo conversions ----------------
__global__ void convert_hilo(const float* __restrict__ src) {
    int i = blockIdx.x * blockDim.x + threadIdx.x;
    float4 v = ((const float4*)src)[i];
    __nv_bfloat16 h0 = __float2bfloat16(v.x), h1 = __float2bfloat16(v.y);
    __nv_bfloat16 h2 = __float2bfloat16(v.z), h3 = __float2bfloat16(v.w);
    __nv_bfloat16 l0 = __float2bfloat16(v.x - __bfloat162float(h0));
    __nv_bfloat16 l1 = __float2bfloat16(v.y - __bfloat162float(h1));
    __nv_bfloat16 l2 = __float2bfloat16(v.z - __bfloat162float(h2));
    __nv_bfloat16 l3 = __float2bfloat16(v.w - __bfloat162float(h3));
    ushort4 hv = { __bfloat16_as_ushort(h0), __bfloat16_as_ushort(h1),
                   __bfloat16_as_ushort(h2), __bfloat16_as_ushort(h3) };
    ushort4 lv = { __bfloat16_as_ushort(l0), __bfloat16_as_ushort(l1),
                   __bfloat16_as_ushort(l2), __bfloat16_as_ushort(l3) };
    ((ushort4*)g_Xhi)[i] = hv;
    ((ushort4*)g_Xlo)[i] = lv;
}

__global__ void convert_T(const float* __restrict__ W, int widx) {
    __shared__ float t[32][33];
    const int k0 = blockIdx.y * 32, n0 = blockIdx.x * 32;
    const int tx = threadIdx.x, ty = threadIdx.y;
#pragma unroll
    for (int j = 0; j < 4; j++)
        t[ty + 8 * j][tx] = W[(size_t)(k0 + ty + 8 * j) * HID + n0 + tx];
    __syncthreads();
#pragma unroll
    for (int j = 0; j < 4; j++) {
        const int n = n0 + ty + 8 * j, k = k0 + tx;
        const float v = t[tx][ty + 8 * j];
        __nv_bfloat16 h = __float2bfloat16(v);
        __nv_bfloat16 l = __float2bfloat16(v - __bfloat162float(h));
        g_WThi[widx][(size_t)n * HID + k] = h;
        g_WTlo[widx][(size_t)n * HID + k] = l;
    }
}

// ---------------- mma.sync split-bf16 GEMM ----------------
#define SROW    80
#define TILE_SM (128 * SROW)
#define STAGE   (4 * TILE_SM)
#define GEMM_SMEM (2 * STAGE)

__global__ __launch_bounds__(256) void mma_gemm(float* __restrict__ Cext, int modeArg) {
    extern __shared__ char sm8[];
    const uint32_t sb = smem_u32(sm8);
    const int tid = threadIdx.x, wid = tid >> 5, lane = tid & 31;
    const int m0 = blockIdx.y * 128, n0 = blockIdx.x * 128;
    const int wm = wid & 1, wn = wid >> 1;
    const int mode = (modeArg < 0) ? (int)blockIdx.z : modeArg;

    const __nv_bfloat16* Ahi = (mode == 3) ? g_AThi : g_Xhi;
    const __nv_bfloat16* Alo = (mode == 3) ? g_ATlo : g_Xlo;
    const __nv_bfloat16* Bhi = g_WThi[mode];
    const __nv_bfloat16* Blo = g_WTlo[mode];

    float acc[4][4][4];
#pragma unroll
    for (int mt = 0; mt < 4; mt++)
#pragma unroll
        for (int nt = 0; nt < 4; nt++)
#pragma unroll
            for (int e = 0; e < 4; e++) acc[mt][nt][e] = 0.f;

#define ISSUE(cc, buf) do {                                                        \
    const int k0_ = (cc) * 32;                                                     \
    const uint32_t s0_ = sb + (buf) * STAGE;                                       \
    _Pragma("unroll")                                                              \
    for (int u = 0; u < 2; u++) {                                                  \
        const int idx = tid + 256 * u;                                             \
        const int r = idx >> 2, c16 = idx & 3;                                     \
        const uint32_t doff = r * SROW + c16 * 16;                                 \
        const size_t aoff = (size_t)(m0 + r) * HID + k0_ + c16 * 8;                \
        const size_t boff = (size_t)(n0 + r) * HID + k0_ + c16 * 8;                \
        CP_ASYNC16(s0_ + doff,               (const char*)&Ahi[aoff]);             \
        CP_ASYNC16(s0_ + TILE_SM + doff,     (const char*)&Alo[aoff]);             \
        CP_ASYNC16(s0_ + 2 * TILE_SM + doff, (const char*)&Bhi[boff]);             \
        CP_ASYNC16(s0_ + 3 * TILE_SM + doff, (const char*)&Blo[boff]);             \
    }                                                                              \
    CP_COMMIT();                                                                   \
} while (0)

    ISSUE(0, 0);
    for (int c = 0; c < 64; c++) {
        const int buf = c & 1;
        if (c < 63) {
            ISSUE(c + 1, buf ^ 1);
            asm volatile("cp.async.wait_group 1;" ::: "memory");
        } else {
            asm volatile("cp.async.wait_group 0;" ::: "memory");
        }
        __syncthreads();

        const uint32_t s0 = sb + buf * STAGE;
        const int kb2 = ((lane >> 4) * 8) * 2;
        const int ar = wm * 64 + (lane & 15);
        const int br = wn * 32 + (lane & 15);
#pragma unroll
        for (int ks = 0; ks < 2; ks++) {
            const int kbyte = ks * 32 + kb2;
            uint32_t ah[4][4], al[4][4];
#pragma unroll
            for (int mt = 0; mt < 4; mt++) {
                const uint32_t addr = s0 + (ar + mt * 16) * SROW + kbyte;
                ldsm4(ah[mt], addr);
                ldsm4(al[mt], addr + TILE_SM);
            }
            uint32_t bh[2][4], bl[2][4];
#pragma unroll
            for (int bt = 0; bt < 2; bt++) {
                const uint32_t addr = s0 + 2 * TILE_SM + (br + bt * 16) * SROW + kbyte;
                ldsm4(bh[bt], addr);
                ldsm4(bl[bt], addr + TILE_SM);
            }
            // chain-outer order: 16 independent accs between dependent MMAs.
            // Fragments already resident -> zero liveness change.
            // Per-acc chain order stays hh, hl, lh -> bitwise identical result.
#pragma unroll
            for (int mt = 0; mt < 4; mt++)
#pragma unroll
                for (int nt = 0; nt < 4; nt++) {
                    const int bt = nt >> 1, sel = nt & 1;
                    mma_bf16(acc[mt][nt], ah[mt], bh[bt][sel], bh[bt][sel + 2]);
                }
#pragma unroll
            for (int mt = 0; mt < 4; mt++)
#pragma unroll
                for (int nt = 0; nt < 4; nt++) {
                    const int bt = nt >> 1, sel = nt & 1;
                    mma_bf16(acc[mt][nt], ah[mt], bl[bt][sel], bl[bt][sel + 2]);
                }
#pragma unroll
            for (int mt = 0; mt < 4; mt++)
#pragma unroll
                for (int nt = 0; nt < 4; nt++) {
                    const int bt = nt >> 1, sel = nt & 1;
                    mma_bf16(acc[mt][nt], al[mt], bh[bt][sel], bh[bt][sel + 2]);
                }
        }
        __syncthreads();
    }

    // ---- epilogue via smem tile ----
    float* Cs = (float*)sm8;   // 128 x 132
#pragma unroll
    for (int mt = 0; mt < 4; mt++)
#pragma unroll
        for (int nt = 0; nt < 4; nt++) {
            const int r = wm * 64 + mt * 16 + (lane >> 2);
            const int col = wn * 32 + nt * 8 + (lane & 3) * 2;
            Cs[r * 132 + col]           = acc[mt][nt][0];
            Cs[r * 132 + col + 1]       = acc[mt][nt][1];
            Cs[(r + 8) * 132 + col]     = acc[mt][nt][2];
            Cs[(r + 8) * 132 + col + 1] = acc[mt][nt][3];
        }
    __syncthreads();

    const int h = blockIdx.x;
    if (mode <= 1) {
        __nv_bfloat16* Ghi = mode ? g_Khi : g_Qhi;
        __nv_bfloat16* Glo = mode ? g_Klo : g_Qlo;
        for (int p = tid; p < 128 * 64; p += 256) {
            const int r = p >> 6, d = p & 63;
            const float v1 = Cs[r * 132 + d];
            const float v2 = Cs[r * 132 + d + 64];
            const int s_ = m0 + r;
            const float invf = expf(-0.14391156831212788f * (float)d);
            const float ang = (float)s_ * invf;
            float sn, cs;
            sincosf(ang, &sn, &cs);
            const float o1 = v1 * cs - v2 * sn;
            const float o2 = v2 * cs + v1 * sn;
            __nv_bfloat16 h1 = __float2bfloat16(o1);
            __nv_bfloat16 h2 = __float2bfloat16(o2);
            __nv_bfloat16 l1 = __float2bfloat16(o1 - __bfloat162float(h1));
            __nv_bfloat16 l2 = __float2bfloat16(o2 - __bfloat162float(h2));
            const size_t base = ((size_t)h * S + s_) * HD;
            Ghi[base + d] = h1; Ghi[base + d + 64] = h2;
            Glo[base + d] = l1; Glo[base + d + 64] = l2;
        }
    } else if (mode == 2) {
        const int d = tid >> 1, seg = tid & 1;
        const size_t base = ((size_t)h * HD + d) * S + m0 + seg * 64;
#pragma unroll
        for (int rr = 0; rr < 16; rr++) {
            ushort4 hv, lv;
            float v0 = Cs[(seg * 64 + rr * 4 + 0) * 132 + d];
            float v1 = Cs[(seg * 64 + rr * 4 + 1) * 132 + d];
            float v2 = Cs[(seg * 64 + rr * 4 + 2) * 132 + d];
            float v3 = Cs[(seg * 64 + rr * 4 + 3) * 132 + d];
            __nv_bfloat16 h0 = __float2bfloat16(v0), h1b = __float2bfloat16(v1);
            __nv_bfloat16 h2b = __float2bfloat16(v2), h3 = __float2bfloat16(v3);
            hv.x = __bfloat16_as_ushort(h0); hv.y = __bfloat16_as_ushort(h1b);
            hv.z = __bfloat16_as_ushort(h2b); hv.w = __bfloat16_as_ushort(h3);
            lv.x = __bfloat16_as_ushort(__float2bfloat16(v0 - __bfloat162float(h0)));
            lv.y = __bfloat16_as_ushort(__float2bfloat16(v1 - __bfloat162float(h1b)));
            lv.z = __bfloat16_as_ushort(__float2bfloat16(v2 - __bfloat162float(h2b)));
            lv.w = __bfloat16_as_ushort(__float2bfloat16(v3 - __bfloat162float(h3)));
            *(ushort4*)&g_Vthi[base + rr * 4] = hv;
            *(ushort4*)&g_Vtlo[base + rr * 4] = lv;
        }
    } else {
        for (int p = tid; p < 128 * 32; p += 256) {
            const int r = p >> 5, c4 = p & 31;
            float4 v = *(float4*)&Cs[r * 132 + c4 * 4];
            *(float4*)&Cext[(size_t)(m0 + r) * HID + n0 + c4 * 4] = v;
        }
    }
}

// ---------------- aux kernels ----------------
__global__ void masklist_kernel(const float* __restrict__ sp) {
    __shared__ float v[1024];
    __shared__ int msk[1024];
    const int h = blockIdx.x, t = threadIdx.x;
    v[t] = sp[h * 1024 + t];
    __syncthreads();
    const float mine = v[t];
    int cnt = 0;
    for (int i = 0; i < 1024; i++) cnt += (v[i] >= mine);
    msk[t] = (cnt <= KSEL) ? 1 : 0;
    __syncthreads();
    if (t < NQB) {
        const int qb = t;
        int c = 0;
        for (int kb = 0; kb < NKB; kb++)
            if (msk[qb * NKB + kb]) g_list[(h * NQB + qb) * NKB + c++] = kb;
        g_cnt[h * NQB + qb] = c;
    }
}

__global__ void vblk_kernel() {
    const int kb = blockIdx.x, h = blockIdx.y, d = threadIdx.x;
    const size_t base = ((size_t)h * HD + d) * S + kb * 64;
    float s = 0.f;
#pragma unroll 8
    for (int r = 0; r < 64; r++)
        s += __bfloat162float(g_Vthi[base + r]) + __bfloat162float(g_Vtlo[base + r]);
    g_Vblk[((size_t)h * NKB + kb) * HD + d] = s;
}
__global__ void vtot_kernel() {
    const int h = blockIdx.x, d = threadIdx.x;
    float s = 0.f;
    for (int kb = 0; kb < NKB; kb++) s += g_Vblk[((size_t)h * NKB + kb) * HD + d];
    g_Vtot[h * HD + d] = s;
}

// ---------------- mma.sync block-sparse attention ----------------
#define QSTR 272
#define VSTR 144
#define AQH 0
#define AQL 17408
#define AKH 34816
#define AKL 52224
#define AVH 69632
#define AVL 88064
#define ASM_SMALL 106496
#define SMEM_ATTN (ASM_SMALL + 64 * 4 + 128 * 4 + 32 * 4)

__global__ __launch_bounds__(128) void attn_mma() {
    extern __shared__ char smb[];
    const uint32_t sb = smem_u32(smb);
    float* lsum  = (float*)(smb + ASM_SMALL);
    float* vcorr = lsum + 64;
    int*   slist = (int*)(vcorr + 128);

    const int qb = blockIdx.x, h = blockIdx.y;
    const int tid = threadIdx.x, wm = tid >> 5, lane = tid & 31;
    const int lrow = lane & 15, lcb = (lane >> 4) << 4;

    const int cnt = g_cnt[h * NQB + qb];
    if (tid < 32) slist[tid] = g_list[(h * NQB + qb) * NKB + tid];

    {
        const size_t gq = ((size_t)h * S + qb * 64) * HD;
#pragma unroll
        for (int u = 0; u < 8; u++) {
            const int idx = tid + 128 * u;
            const int r = idx >> 4, c = idx & 15;
            CP_ASYNC16(sb + AQH + r * QSTR + c * 16, (const char*)&g_Qhi[gq + (size_t)r * HD + c * 8]);
            CP_ASYNC16(sb + AQL + r * QSTR + c * 16, (const char*)&g_Qlo[gq + (size_t)r * HD + c * 8]);
        }
        CP_COMMIT();
    }
    __syncthreads();

    {
        float vc = g_Vtot[h * HD + tid];
        for (int ii = 0; ii < cnt; ii++)
            vc -= g_Vblk[((size_t)h * NKB + slist[ii]) * HD + tid];
        vcorr[tid] = vc;
        if (tid < 64) lsum[tid] = (float)(S - 64 * cnt);
    }
    __syncthreads();

    float oacc[16][4];
#pragma unroll
    for (int i = 0; i < 16; i++)
#pragma unroll
        for (int e = 0; e < 4; e++) oacc[i][e] = 0.f;

    for (int ii = 0; ii < cnt; ii++) {
        const int kb = slist[ii];
        const size_t gk = ((size_t)h * S + kb * 64) * HD;
        const size_t gv = (size_t)h * HD * S + (size_t)kb * 64;
#pragma unroll
        for (int u = 0; u < 8; u++) {
            const int idx = tid + 128 * u;
            const int r = idx >> 4, c = idx & 15;
            CP_ASYNC16(sb + AKH + r * QSTR + c * 16, (const char*)&g_Khi[gk + (size_t)r * HD + c * 8]);
            CP_ASYNC16(sb + AKL + r * QSTR + c * 16, (const char*)&g_Klo[gk + (size_t)r * HD + c * 8]);
            const int rv = idx >> 3, cv = idx & 7;
            CP_ASYNC16(sb + AVH + rv * VSTR + cv * 16, (const char*)&g_Vthi[gv + (size_t)rv * S + cv * 8]);
            CP_ASYNC16(sb + AVL + rv * VSTR + cv * 16, (const char*)&g_Vtlo[gv + (size_t)rv * S + cv * 8]);
        }
        CP_COMMIT();
        asm volatile("cp.async.wait_group 0;" ::: "memory");
        __syncthreads();

        // S = Q K^T — interleave the two accumulators (dependency distance 2)
        float sacc[8][4];
#pragma unroll
        for (int i = 0; i < 8; i++)
#pragma unroll
            for (int e = 0; e < 4; e++) sacc[i][e] = 0.f;
#pragma unroll
        for (int kt = 0; kt < 8; kt++) {
            uint32_t qh[4], ql[4];
            const uint32_t qa = sb + AQH + (wm * 16 + lrow) * QSTR + kt * 32 + lcb;
            ldsm4(qh, qa);
            ldsm4(ql, qa + (AQL - AQH));
#pragma unroll
            for (int jt = 0; jt < 4; jt++) {
                uint32_t kh[4], kl[4];
                const uint32_t ka = sb + AKH + (jt * 16 + lrow) * QSTR + kt * 32 + lcb;
                ldsm4(kh, ka);
                ldsm4(kl, ka + (AKL - AKH));
                mma_bf16(sacc[2 * jt],     qh, kh[0], kh[2]);
                mma_bf16(sacc[2 * jt + 1], qh, kh[1], kh[3]);
                mma_bf16(sacc[2 * jt],     qh, kl[0], kl[2]);
                mma_bf16(sacc[2 * jt + 1], qh, kl[1], kl[3]);
                mma_bf16(sacc[2 * jt],     ql, kh[0], kh[2]);
                mma_bf16(sacc[2 * jt + 1], ql, kh[1], kh[3]);
            }
        }

        uint32_t pah[4][4], pal[4][4];
        float rs0 = 0.f, rs1 = 0.f;
#pragma unroll
        for (int nt = 0; nt < 8; nt++) {
            const float p0 = __expf(sacc[nt][0] * SCALE);
            const float p1 = __expf(sacc[nt][1] * SCALE);
            const float p2 = __expf(sacc[nt][2] * SCALE);
            const float p3 = __expf(sacc[nt][3] * SCALE);
            rs0 += p0 + p1;
            rs1 += p2 + p3;
            const int g = nt >> 1, o = (nt & 1) * 2;
            split2(p0, p1, pah[g][o],     pal[g][o]);
            split2(p2, p3, pah[g][o + 1], pal[g][o + 1]);
        }
        rs0 += __shfl_xor_sync(0xffffffffu, rs0, 1);
        rs0 += __shfl_xor_sync(0xffffffffu, rs0, 2);
        rs1 += __shfl_xor_sync(0xffffffffu, rs1, 1);
        rs1 += __shfl_xor_sync(0xffffffffu, rs1, 2);
        if ((lane & 3) == 0) {
            lsum[wm * 16 + (lane >> 2)]     += rs0;
            lsum[wm * 16 + (lane >> 2) + 8] += rs1;
        }

        // O += P V — interleave the two accumulators per dt
#pragma unroll
        for (int g = 0; g < 4; g++) {
#pragma unroll
            for (int dt = 0; dt < 8; dt++) {
                uint32_t vh[4], vl[4];
                const uint32_t va = sb + AVH + (dt * 16 + lrow) * VSTR + g * 32 + lcb;
                ldsm4(vh, va);
                ldsm4(vl, va + (AVL - AVH));
                mma_bf16(oacc[2 * dt],     pah[g], vh[0], vh[2]);
                mma_bf16(oacc[2 * dt + 1], pah[g], vh[1], vh[3]);
                mma_bf16(oacc[2 * dt],     pal[g], vh[0], vh[2]);
                mma_bf16(oacc[2 * dt + 1], pal[g], vh[1], vh[3]);
                mma_bf16(oacc[2 * dt],     pah[g], vl[0], vl[2]);
                mma_bf16(oacc[2 * dt + 1], pah[g], vl[1], vl[3]);
            }
        }
        __syncthreads();
    }
    asm volatile("cp.async.wait_group 0;" ::: "memory");
    __syncthreads();

    // normalize + zero-block correction, write split-bf16 directly
    const int r0 = wm * 16 + (lane >> 2);
    const float il0 = 1.f / lsum[r0];
    const float il1 = 1.f / lsum[r0 + 8];
    const int cbase = 2 * (lane & 3);
    const size_t ob0 = (size_t)(qb * 64 + r0) * HID + h * HD;
    const size_t ob1 = ob0 + (size_t)8 * HID;
#pragma unroll
    for (int ot = 0; ot < 16; ot++) {
        const int c = 8 * ot + cbase;
        const float a0 = (oacc[ot][0] + vcorr[c]) * il0;
        const float a1 = (oacc[ot][1] + vcorr[c + 1]) * il0;
        const float b0 = (oacc[ot][2] + vcorr[c]) * il1;
        const float b1 = (oacc[ot][3] + vcorr[c + 1]) * il1;
        uint32_t hi, lo;
        split2(a0, a1, hi, lo);
        ((uint32_t*)g_AThi)[(ob0 + c) >> 1] = hi;
        ((uint32_t*)g_ATlo)[(ob0 + c) >> 1] = lo;
        split2(b0, b1, hi, lo);
        ((uint32_t*)g_AThi)[(ob1 + c) >> 1] = hi;
        ((uint32_t*)g_ATlo)[(ob1 + c) >> 1] = lo;
    }
}

// ---------------------------------------------------------------------------
extern "C" void kernel_launch(void* const* d_in, const int* in_sizes, int n_in,
                              void* d_out, int out_size) {
    const float* X  = (const float*)d_in[0];
    const float* qw = (const float*)d_in[1];
    const float* kw = (const float*)d_in[2];
    const float* vw = (const float*)d_in[3];
    const float* ow = (const float*)d_in[4];
    const float* sp = (const float*)d_in[5];
    float* out = (float*)d_out;

    cudaFuncSetAttribute(mma_gemm, cudaFuncAttributeMaxDynamicSharedMemorySize, GEMM_SMEM);
    cudaFuncSetAttribute(attn_mma, cudaFuncAttributeMaxDynamicSharedMemorySize, SMEM_ATTN);

    dim3 tg(64, 64), tb(32, 8);
    convert_hilo<<<(S * HID / 4 + 255) / 256, 256>>>(X);
    convert_T<<<tg, tb>>>(qw, 0);
    convert_T<<<tg, tb>>>(kw, 1);
    convert_T<<<tg, tb>>>(vw, 2);
    convert_T<<<tg, tb>>>(ow, 3);
    mma_gemm<<<dim3(16, 16, 3), 256, GEMM_SMEM>>>(nullptr, -1);
    masklist_kernel<<<NH, 1024>>>(sp);
    vblk_kernel<<<dim3(NKB, NH), HD>>>();
    vtot_kernel<<<NH, HD>>>();
    attn_mma<<<dim3(NQB, NH), 128, SMEM_ATTN>>>();
    mma_gemm<<<dim3(16, 16), 256, GEMM_SMEM>>>(out, 3);
}

// round 11
// speedup vs baseline: 1.4281x; 1.4281x over previous
#include <cuda_runtime.h>
#include <cuda_fp16.h>
#include <math.h>
#include <stdint.h>

// Problem constants
#define S     2048
#define HID   2048
#define NH    16
#define HD    128
#define BS_   64
#define NQB   32
#define NKB   32
#define KSEL  511
#define SCALE 0.08838834764831845f
#define ESHIFT 4.0f
#define EXPC  0.01831563889f   // e^-4

// ---------------- device scratch (allocation-free) ----------------
__device__ float g_Vblk[NH * NKB * HD];
__device__ float g_Vtot[NH * HD];
__device__ int   g_list[NH * NQB * NKB];
__device__ int   g_cnt[NH * NQB];

// fp16 operands: A-side plain fp16, B-side split hi/lo
__device__ __half g_Xh[S * HID];                         // X, fp16 (A of QKV gemms)
__device__ __half g_Wh[4][HID * HID], g_Wl[4][HID * HID];// W^T [N,K] split (B)
__device__ __half g_ATh[S * HID];                        // attn out, fp16 (A of O gemm)

__device__ __half g_Qh[NH * S * HD];                     // Q RoPE'd, fp16 (A of QK)
__device__ __half g_Kh[NH * S * HD], g_Kl[NH * S * HD];  // K RoPE'd split (B of QK)
__device__ __half g_Vth[NH * HD * S], g_Vtl[NH * HD * S];// V^T [h][d][s] split (B of PV)

// ---------------- helpers ----------------
__device__ __forceinline__ uint32_t smem_u32(const void* p) {
    uint32_t a;
    asm("{ .reg .u64 t; cvta.to.shared.u64 t, %1; cvt.u32.u64 %0, t; }" : "=r"(a) : "l"(p));
    return a;
}
__device__ __forceinline__ void ldsm4(uint32_t (&r)[4], uint32_t addr) {
    asm volatile("ldmatrix.sync.aligned.m8n8.x4.shared.b16 {%0,%1,%2,%3}, [%4];"
        : "=r"(r[0]), "=r"(r[1]), "=r"(r[2]), "=r"(r[3]) : "r"(addr));
}
__device__ __forceinline__ void mma_f16(float (&d)[4], const uint32_t (&a)[4],
                                        uint32_t b0, uint32_t b1) {
    asm volatile("mma.sync.aligned.m16n8k16.row.col.f32.f16.f16.f32 "
        "{%0,%1,%2,%3}, {%4,%5,%6,%7}, {%8,%9}, {%0,%1,%2,%3};"
        : "+f"(d[0]), "+f"(d[1]), "+f"(d[2]), "+f"(d[3])
        : "r"(a[0]), "r"(a[1]), "r"(a[2]), "r"(a[3]), "r"(b0), "r"(b1));
}
#define CP_ASYNC16(dst, src) \
    asm volatile("cp.async.cg.shared.global [%0], [%1], 16;" :: "r"(dst), "l"(src))
#define CP_COMMIT() asm volatile("cp.async.commit_group;" ::: "memory")

__device__ __forceinline__ uint32_t packh2(float a, float b) {
    __half2 h = __floats2half2_rn(a, b);   // low = a, high = b
    return *reinterpret_cast<uint32_t*>(&h);
}

// ---------------- conversions ----------------
__global__ void convert_h(const float* __restrict__ src) {
    int i = blockIdx.x * blockDim.x + threadIdx.x;
    float4 v = ((const float4*)src)[i];
    ushort4 hv = { __half_as_ushort(__float2half_rn(v.x)),
                   __half_as_ushort(__float2half_rn(v.y)),
                   __half_as_ushort(__float2half_rn(v.z)),
                   __half_as_ushort(__float2half_rn(v.w)) };
    ((ushort4*)g_Xh)[i] = hv;
}

__global__ void convert_T(const float* __restrict__ W, int widx) {
    __shared__ float t[32][33];
    const int k0 = blockIdx.y * 32, n0 = blockIdx.x * 32;
    const int tx = threadIdx.x, ty = threadIdx.y;
#pragma unroll
    for (int j = 0; j < 4; j++)
        t[ty + 8 * j][tx] = W[(size_t)(k0 + ty + 8 * j) * HID + n0 + tx];
    __syncthreads();
#pragma unroll
    for (int j = 0; j < 4; j++) {
        const int n = n0 + ty + 8 * j, k = k0 + tx;
        const float v = t[tx][ty + 8 * j];
        __half h = __float2half_rn(v);
        __half l = __float2half_rn(v - __half2float(h));
        g_Wh[widx][(size_t)n * HID + k] = h;
        g_Wl[widx][(size_t)n * HID + k] = l;
    }
}

// ---------------- mma.sync fp16 2-chain GEMM ----------------
// A plain fp16 (1 tile), B split hi/lo (2 tiles). BK=32, 2-stage cp.async.
#define SROW    80
#define TILE_SM (128 * SROW)
#define STAGE   (3 * TILE_SM)       // 30720
#define GEMM_SMEM 69632             // max(2*STAGE, 128*132*4 epilogue)

__global__ __launch_bounds__(256) void mma_gemm(float* __restrict__ Cext, int modeArg) {
    extern __shared__ char sm8[];
    const uint32_t sb = smem_u32(sm8);
    const int tid = threadIdx.x, wid = tid >> 5, lane = tid & 31;
    const int m0 = blockIdx.y * 128, n0 = blockIdx.x * 128;
    const int wm = wid & 1, wn = wid >> 1;
    const int mode = (modeArg < 0) ? (int)blockIdx.z : modeArg;

    const __half* Ah = (mode == 3) ? g_ATh : g_Xh;
    const __half* Bh = g_Wh[mode];
    const __half* Bl = g_Wl[mode];

    float acc[4][4][4];
#pragma unroll
    for (int mt = 0; mt < 4; mt++)
#pragma unroll
        for (int nt = 0; nt < 4; nt++)
#pragma unroll
            for (int e = 0; e < 4; e++) acc[mt][nt][e] = 0.f;

#define ISSUE(cc, buf) do {                                                        \
    const int k0_ = (cc) * 32;                                                     \
    const uint32_t s0_ = sb + (buf) * STAGE;                                       \
    _Pragma("unroll")                                                              \
    for (int u = 0; u < 2; u++) {                                                  \
        const int idx = tid + 256 * u;                                             \
        const int r = idx >> 2, c16 = idx & 3;                                     \
        const uint32_t doff = r * SROW + c16 * 16;                                 \
        const size_t aoff = (size_t)(m0 + r) * HID + k0_ + c16 * 8;                \
        const size_t boff = (size_t)(n0 + r) * HID + k0_ + c16 * 8;                \
        CP_ASYNC16(s0_ + doff,               (const char*)&Ah[aoff]);              \
        CP_ASYNC16(s0_ + TILE_SM + doff,     (const char*)&Bh[boff]);              \
        CP_ASYNC16(s0_ + 2 * TILE_SM + doff, (const char*)&Bl[boff]);              \
    }                                                                              \
    CP_COMMIT();                                                                   \
} while (0)

    ISSUE(0, 0);
    for (int c = 0; c < 64; c++) {
        const int buf = c & 1;
        if (c < 63) {
            ISSUE(c + 1, buf ^ 1);
            asm volatile("cp.async.wait_group 1;" ::: "memory");
        } else {
            asm volatile("cp.async.wait_group 0;" ::: "memory");
        }
        __syncthreads();

        const uint32_t s0 = sb + buf * STAGE;
        const int kb2 = ((lane >> 4) * 8) * 2;
        const int ar = wm * 64 + (lane & 15);
        const int br = wn * 32 + (lane & 15);
#pragma unroll
        for (int ks = 0; ks < 2; ks++) {
            const int kbyte = ks * 32 + kb2;
            uint32_t ah[4][4];
#pragma unroll
            for (int mt = 0; mt < 4; mt++)
                ldsm4(ah[mt], s0 + (ar + mt * 16) * SROW + kbyte);
            uint32_t bh[2][4], bl[2][4];
#pragma unroll
            for (int bt = 0; bt < 2; bt++) {
                const uint32_t addr = s0 + TILE_SM + (br + bt * 16) * SROW + kbyte;
                ldsm4(bh[bt], addr);
                ldsm4(bl[bt], addr + TILE_SM);
            }
#pragma unroll
            for (int mt = 0; mt < 4; mt++)
#pragma unroll
                for (int nt = 0; nt < 4; nt++) {
                    const int bt = nt >> 1, sel = nt & 1;
                    mma_f16(acc[mt][nt], ah[mt], bh[bt][sel], bh[bt][sel + 2]);
                }
#pragma unroll
            for (int mt = 0; mt < 4; mt++)
#pragma unroll
                for (int nt = 0; nt < 4; nt++) {
                    const int bt = nt >> 1, sel = nt & 1;
                    mma_f16(acc[mt][nt], ah[mt], bl[bt][sel], bl[bt][sel + 2]);
                }
        }
        __syncthreads();
    }

    // ---- epilogue via smem tile ----
    float* Cs = (float*)sm8;   // 128 x 132
#pragma unroll
    for (int mt = 0; mt < 4; mt++)
#pragma unroll
        for (int nt = 0; nt < 4; nt++) {
            const int r = wm * 64 + mt * 16 + (lane >> 2);
            const int col = wn * 32 + nt * 8 + (lane & 3) * 2;
            Cs[r * 132 + col]           = acc[mt][nt][0];
            Cs[r * 132 + col + 1]       = acc[mt][nt][1];
            Cs[(r + 8) * 132 + col]     = acc[mt][nt][2];
            Cs[(r + 8) * 132 + col + 1] = acc[mt][nt][3];
        }
    __syncthreads();

    const int h = blockIdx.x;
    if (mode <= 1) {
        for (int p = tid; p < 128 * 64; p += 256) {
            const int r = p >> 6, d = p & 63;
            const float v1 = Cs[r * 132 + d];
            const float v2 = Cs[r * 132 + d + 64];
            const int s_ = m0 + r;
            const float invf = expf(-0.14391156831212788f * (float)d);
            const float ang = (float)s_ * invf;
            float sn, cs;
            sincosf(ang, &sn, &cs);
            const float o1 = v1 * cs - v2 * sn;
            const float o2 = v2 * cs + v1 * sn;
            const size_t base = ((size_t)h * S + s_) * HD;
            if (mode == 0) {
                g_Qh[base + d]      = __float2half_rn(o1);
                g_Qh[base + d + 64] = __float2half_rn(o2);
            } else {
                __half h1 = __float2half_rn(o1);
                __half h2 = __float2half_rn(o2);
                g_Kh[base + d]      = h1;
                g_Kh[base + d + 64] = h2;
                g_Kl[base + d]      = __float2half_rn(o1 - __half2float(h1));
                g_Kl[base + d + 64] = __float2half_rn(o2 - __half2float(h2));
            }
        }
    } else if (mode == 2) {
        const int d = tid >> 1, seg = tid & 1;
        const size_t base = ((size_t)h * HD + d) * S + m0 + seg * 64;
#pragma unroll
        for (int rr = 0; rr < 16; rr++) {
            ushort4 hv, lv;
            float v0 = Cs[(seg * 64 + rr * 4 + 0) * 132 + d];
            float v1 = Cs[(seg * 64 + rr * 4 + 1) * 132 + d];
            float v2 = Cs[(seg * 64 + rr * 4 + 2) * 132 + d];
            float v3 = Cs[(seg * 64 + rr * 4 + 3) * 132 + d];
            __half h0 = __float2half_rn(v0), h1b = __float2half_rn(v1);
            __half h2b = __float2half_rn(v2), h3 = __float2half_rn(v3);
            hv.x = __half_as_ushort(h0); hv.y = __half_as_ushort(h1b);
            hv.z = __half_as_ushort(h2b); hv.w = __half_as_ushort(h3);
            lv.x = __half_as_ushort(__float2half_rn(v0 - __half2float(h0)));
            lv.y = __half_as_ushort(__float2half_rn(v1 - __half2float(h1b)));
            lv.z = __half_as_ushort(__float2half_rn(v2 - __half2float(h2b)));
            lv.w = __half_as_ushort(__float2half_rn(v3 - __half2float(h3)));
            *(ushort4*)&g_Vth[base + rr * 4] = hv;
            *(ushort4*)&g_Vtl[base + rr * 4] = lv;
        }
    } else {
        for (int p = tid; p < 128 * 32; p += 256) {
            const int r = p >> 5, c4 = p & 31;
            float4 v = *(float4*)&Cs[r * 132 + c4 * 4];
            *(float4*)&Cext[(size_t)(m0 + r) * HID + n0 + c4 * 4] = v;
        }
    }
}

// ---------------- aux kernels ----------------
__global__ void masklist_kernel(const float* __restrict__ sp) {
    __shared__ float v[1024];
    __shared__ int msk[1024];
    const int h = blockIdx.x, t = threadIdx.x;
    v[t] = sp[h * 1024 + t];
    __syncthreads();
    const float mine = v[t];
    int cnt = 0;
    for (int i = 0; i < 1024; i++) cnt += (v[i] >= mine);
    msk[t] = (cnt <= KSEL) ? 1 : 0;
    __syncthreads();
    if (t < NQB) {
        const int qb = t;
        int c = 0;
        for (int kb = 0; kb < NKB; kb++)
            if (msk[qb * NKB + kb]) g_list[(h * NQB + qb) * NKB + c++] = kb;
        g_cnt[h * NQB + qb] = c;
    }
}

__global__ void vblk_kernel() {
    const int kb = blockIdx.x, h = blockIdx.y, d = threadIdx.x;
    const size_t base = ((size_t)h * HD + d) * S + kb * 64;
    float s = 0.f;
#pragma unroll 8
    for (int r = 0; r < 64; r++)
        s += __half2float(g_Vth[base + r]) + __half2float(g_Vtl[base + r]);
    g_Vblk[((size_t)h * NKB + kb) * HD + d] = s;
}
__global__ void vtot_kernel() {
    const int h = blockIdx.x, d = threadIdx.x;
    float s = 0.f;
    for (int kb = 0; kb < NKB; kb++) s += g_Vblk[((size_t)h * NKB + kb) * HD + d];
    g_Vtot[h * HD + d] = s;
}

// ---------------- mma.sync block-sparse attention (fp16, 2-chain) ----------------
#define QSTR 272
#define VSTR 144
#define AQ  0
#define AKH 17408
#define AKL 34816
#define AVH 52224
#define AVL 70656
#define ASM_SMALL 89088
#define SMEM_ATTN (ASM_SMALL + 64 * 4 + 128 * 4 + 32 * 4)

__global__ __launch_bounds__(128) void attn_mma() {
    extern __shared__ char smb[];
    const uint32_t sb = smem_u32(smb);
    float* lsum  = (float*)(smb + ASM_SMALL);
    float* vcorr = lsum + 64;
    int*   slist = (int*)(vcorr + 128);

    const int qb = blockIdx.x, h = blockIdx.y;
    const int tid = threadIdx.x, wm = tid >> 5, lane = tid & 31;
    const int lrow = lane & 15, lcb = (lane >> 4) << 4;

    const int cnt = g_cnt[h * NQB + qb];
    if (tid < 32) slist[tid] = g_list[(h * NQB + qb) * NKB + tid];

    {
        const size_t gq = ((size_t)h * S + qb * 64) * HD;
#pragma unroll
        for (int u = 0; u < 8; u++) {
            const int idx = tid + 128 * u;
            const int r = idx >> 4, c = idx & 15;
            CP_ASYNC16(sb + AQ + r * QSTR + c * 16, (const char*)&g_Qh[gq + (size_t)r * HD + c * 8]);
        }
        CP_COMMIT();
    }
    __syncthreads();

    {
        float vc = g_Vtot[h * HD + tid];
        for (int ii = 0; ii < cnt; ii++)
            vc -= g_Vblk[((size_t)h * NKB + slist[ii]) * HD + tid];
        vcorr[tid] = vc * EXPC;                      // zero-block term, e^-4 shifted
        if (tid < 64) lsum[tid] = (float)(S - 64 * cnt) * EXPC;
    }
    __syncthreads();

    float oacc[16][4];
#pragma unroll
    for (int i = 0; i < 16; i++)
#pragma unroll
        for (int e = 0; e < 4; e++) oacc[i][e] = 0.f;

    for (int ii = 0; ii < cnt; ii++) {
        const int kb = slist[ii];
        const size_t gk = ((size_t)h * S + kb * 64) * HD;
        const size_t gv = (size_t)h * HD * S + (size_t)kb * 64;
#pragma unroll
        for (int u = 0; u < 8; u++) {
            const int idx = tid + 128 * u;
            const int r = idx >> 4, c = idx & 15;
            CP_ASYNC16(sb + AKH + r * QSTR + c * 16, (const char*)&g_Kh[gk + (size_t)r * HD + c * 8]);
            CP_ASYNC16(sb + AKL + r * QSTR + c * 16, (const char*)&g_Kl[gk + (size_t)r * HD + c * 8]);
            const int rv = idx >> 3, cv = idx & 7;
            CP_ASYNC16(sb + AVH + rv * VSTR + cv * 16, (const char*)&g_Vth[gv + (size_t)rv * S + cv * 8]);
            CP_ASYNC16(sb + AVL + rv * VSTR + cv * 16, (const char*)&g_Vtl[gv + (size_t)rv * S + cv * 8]);
        }
        CP_COMMIT();
        asm volatile("cp.async.wait_group 0;" ::: "memory");
        __syncthreads();

        // S = Q K^T : qh·kh + qh·kl
        float sacc[8][4];
#pragma unroll
        for (int i = 0; i < 8; i++)
#pragma unroll
            for (int e = 0; e < 4; e++) sacc[i][e] = 0.f;
#pragma unroll
        for (int kt = 0; kt < 8; kt++) {
            uint32_t qh[4];
            ldsm4(qh, sb + AQ + (wm * 16 + lrow) * QSTR + kt * 32 + lcb);
#pragma unroll
            for (int jt = 0; jt < 4; jt++) {
                uint32_t kh[4], kl[4];
                const uint32_t ka = sb + AKH + (jt * 16 + lrow) * QSTR + kt * 32 + lcb;
                ldsm4(kh, ka);
                ldsm4(kl, ka + (AKL - AKH));
                mma_f16(sacc[2 * jt],     qh, kh[0], kh[2]);
                mma_f16(sacc[2 * jt + 1], qh, kh[1], kh[3]);
                mma_f16(sacc[2 * jt],     qh, kl[0], kl[2]);
                mma_f16(sacc[2 * jt + 1], qh, kl[1], kl[3]);
            }
        }

        // exp with e^-4 shift (fp16 range safety), pack P to fp16
        uint32_t pah[4][4];
        float rs0 = 0.f, rs1 = 0.f;
#pragma unroll
        for (int nt = 0; nt < 8; nt++) {
            const float p0 = __expf(fmaf(sacc[nt][0], SCALE, -ESHIFT));
            const float p1 = __expf(fmaf(sacc[nt][1], SCALE, -ESHIFT));
            const float p2 = __expf(fmaf(sacc[nt][2], SCALE, -ESHIFT));
            const float p3 = __expf(fmaf(sacc[nt][3], SCALE, -ESHIFT));
            rs0 += p0 + p1;
            rs1 += p2 + p3;
            const int g = nt >> 1, o = (nt & 1) * 2;
            pah[g][o]     = packh2(p0, p1);
            pah[g][o + 1] = packh2(p2, p3);
        }
        rs0 += __shfl_xor_sync(0xffffffffu, rs0, 1);
        rs0 += __shfl_xor_sync(0xffffffffu, rs0, 2);
        rs1 += __shfl_xor_sync(0xffffffffu, rs1, 1);
        rs1 += __shfl_xor_sync(0xffffffffu, rs1, 2);
        if ((lane & 3) == 0) {
            lsum[wm * 16 + (lane >> 2)]     += rs0;
            lsum[wm * 16 + (lane >> 2) + 8] += rs1;
        }

        // O += P V : ph·vh + ph·vl
#pragma unroll
        for (int g = 0; g < 4; g++) {
#pragma unroll
            for (int dt = 0; dt < 8; dt++) {
                uint32_t vh[4], vl[4];
                const uint32_t va = sb + AVH + (dt * 16 + lrow) * VSTR + g * 32 + lcb;
                ldsm4(vh, va);
                ldsm4(vl, va + (AVL - AVH));
                mma_f16(oacc[2 * dt],     pah[g], vh[0], vh[2]);
                mma_f16(oacc[2 * dt + 1], pah[g], vh[1], vh[3]);
                mma_f16(oacc[2 * dt],     pah[g], vl[0], vl[2]);
                mma_f16(oacc[2 * dt + 1], pah[g], vl[1], vl[3]);
            }
        }
        __syncthreads();
    }
    asm volatile("cp.async.wait_group 0;" ::: "memory");
    __syncthreads();

    // normalize + zero-block correction, write fp16 A-operand directly
    const int r0 = wm * 16 + (lane >> 2);
    const float il0 = 1.f / lsum[r0];
    const float il1 = 1.f / lsum[r0 + 8];
    const int cbase = 2 * (lane & 3);
    const size_t ob0 = (size_t)(qb * 64 + r0) * HID + h * HD;
    const size_t ob1 = ob0 + (size_t)8 * HID;
#pragma unroll
    for (int ot = 0; ot < 16; ot++) {
        const int c = 8 * ot + cbase;
        const float a0 = (oacc[ot][0] + vcorr[c]) * il0;
        const float a1 = (oacc[ot][1] + vcorr[c + 1]) * il0;
        const float b0 = (oacc[ot][2] + vcorr[c]) * il1;
        const float b1 = (oacc[ot][3] + vcorr[c + 1]) * il1;
        ((uint32_t*)g_ATh)[(ob0 + c) >> 1] = packh2(a0, a1);
        ((uint32_t*)g_ATh)[(ob1 + c) >> 1] = packh2(b0, b1);
    }
}

// ---------------------------------------------------------------------------
extern "C" void kernel_launch(void* const* d_in, const int* in_sizes, int n_in,
                              void* d_out, int out_size) {
    const float* X  = (const float*)d_in[0];
    const float* qw = (const float*)d_in[1];
    const float* kw = (const float*)d_in[2];
    const float* vw = (const float*)d_in[3];
    const float* ow = (const float*)d_in[4];
    const float* sp = (const float*)d_in[5];
    float* out = (float*)d_out;

    cudaFuncSetAttribute(mma_gemm, cudaFuncAttributeMaxDynamicSharedMemorySize, GEMM_SMEM);
    cudaFuncSetAttribute(attn_mma, cudaFuncAttributeMaxDynamicSharedMemorySize, SMEM_ATTN);

    dim3 tg(64, 64), tb(32, 8);
    convert_h<<<(S * HID / 4 + 255) / 256, 256>>>(X);
    convert_T<<<tg, tb>>>(qw, 0);
    convert_T<<<tg, tb>>>(kw, 1);
    convert_T<<<tg, tb>>>(vw, 2);
    convert_T<<<tg, tb>>>(ow, 3);
    mma_gemm<<<dim3(16, 16, 3), 256, GEMM_SMEM>>>(nullptr, -1);
    masklist_kernel<<<NH, 1024>>>(sp);
    vblk_kernel<<<dim3(NKB, NH), HD>>>();
    vtot_kernel<<<NH, HD>>>();
    attn_mma<<<dim3(NQB, NH), 128, SMEM_ATTN>>>();
    mma_gemm<<<dim3(16, 16), 256, GEMM_SMEM>>>(out, 3);
}

// round 12
// speedup vs baseline: 1.4816x; 1.0375x over previous
#include <cuda_runtime.h>
#include <cuda_fp16.h>
#include <math.h>
#include <stdint.h>

// Problem constants
#define S     2048
#define HID   2048
#define NH    16
#define HD    128
#define BS_   64
#define NQB   32
#define NKB   32
#define KSEL  511
#define SCALE 0.08838834764831845f
#define ESHIFT 4.0f
#define EXPC  0.01831563889f   // e^-4

// ---------------- device scratch (allocation-free) ----------------
__device__ float g_Vblk[NH * NKB * HD];
__device__ float g_Vtot[NH * HD];
__device__ int   g_list[NH * NQB * NKB];
__device__ int   g_cnt[NH * NQB];

// fp16 operands: A-side plain fp16, B-side split hi/lo
__device__ __half g_Xh[S * HID];
__device__ __half g_Wh[4][HID * HID], g_Wl[4][HID * HID];
__device__ __half g_ATh[S * HID];

__device__ __half g_Qh[NH * S * HD];
__device__ __half g_Kh[NH * S * HD], g_Kl[NH * S * HD];
__device__ __half g_Vth[NH * HD * S], g_Vtl[NH * HD * S];

// ---------------- helpers ----------------
__device__ __forceinline__ uint32_t smem_u32(const void* p) {
    uint32_t a;
    asm("{ .reg .u64 t; cvta.to.shared.u64 t, %1; cvt.u32.u64 %0, t; }" : "=r"(a) : "l"(p));
    return a;
}
__device__ __forceinline__ void ldsm4(uint32_t (&r)[4], uint32_t addr) {
    asm volatile("ldmatrix.sync.aligned.m8n8.x4.shared.b16 {%0,%1,%2,%3}, [%4];"
        : "=r"(r[0]), "=r"(r[1]), "=r"(r[2]), "=r"(r[3]) : "r"(addr));
}
__device__ __forceinline__ void mma_f16(float (&d)[4], const uint32_t (&a)[4],
                                        uint32_t b0, uint32_t b1) {
    asm volatile("mma.sync.aligned.m16n8k16.row.col.f32.f16.f16.f32 "
        "{%0,%1,%2,%3}, {%4,%5,%6,%7}, {%8,%9}, {%0,%1,%2,%3};"
        : "+f"(d[0]), "+f"(d[1]), "+f"(d[2]), "+f"(d[3])
        : "r"(a[0]), "r"(a[1]), "r"(a[2]), "r"(a[3]), "r"(b0), "r"(b1));
}
#define CP_ASYNC16(dst, src) \
    asm volatile("cp.async.cg.shared.global [%0], [%1], 16;" :: "r"(dst), "l"(src))
#define CP_COMMIT() asm volatile("cp.async.commit_group;" ::: "memory")

__device__ __forceinline__ uint32_t packh2(float a, float b) {
    __half2 h = __floats2half2_rn(a, b);
    return *reinterpret_cast<uint32_t*>(&h);
}

// ---------------- conversions ----------------
__global__ void convert_h(const float* __restrict__ src) {
    int i = blockIdx.x * blockDim.x + threadIdx.x;
    float4 v = ((const float4*)src)[i];
    ushort4 hv = { __half_as_ushort(__float2half_rn(v.x)),
                   __half_as_ushort(__float2half_rn(v.y)),
                   __half_as_ushort(__float2half_rn(v.z)),
                   __half_as_ushort(__float2half_rn(v.w)) };
    ((ushort4*)g_Xh)[i] = hv;
}

// all 4 weight transposes in one launch (z = which weight)
__global__ void convert_T4(const float* __restrict__ qw, const float* __restrict__ kw,
                           const float* __restrict__ vw, const float* __restrict__ ow) {
    __shared__ float t[32][33];
    const int widx = blockIdx.z;
    const float* W = (widx == 0) ? qw : (widx == 1) ? kw : (widx == 2) ? vw : ow;
    const int k0 = blockIdx.y * 32, n0 = blockIdx.x * 32;
    const int tx = threadIdx.x, ty = threadIdx.y;
#pragma unroll
    for (int j = 0; j < 4; j++)
        t[ty + 8 * j][tx] = W[(size_t)(k0 + ty + 8 * j) * HID + n0 + tx];
    __syncthreads();
#pragma unroll
    for (int j = 0; j < 4; j++) {
        const int n = n0 + ty + 8 * j, k = k0 + tx;
        const float v = t[tx][ty + 8 * j];
        __half h = __float2half_rn(v);
        __half l = __float2half_rn(v - __half2float(h));
        g_Wh[widx][(size_t)n * HID + k] = h;
        g_Wl[widx][(size_t)n * HID + k] = l;
    }
}

// ---------------- mma.sync fp16 GEMM, 3-stage pipeline ----------------
// modes 0..2: 2 chains (B split). mode 3 (O proj): 1 chain (B rounded).
#define SROW    80
#define TILE_SM (128 * SROW)
#define STAGE   (3 * TILE_SM)       // 30720
#define GEMM_SMEM (3 * STAGE)       // 92160 >= epilogue 67584

__global__ __launch_bounds__(256) void mma_gemm(float* __restrict__ Cext, int modeArg) {
    extern __shared__ char sm8[];
    const uint32_t sb = smem_u32(sm8);
    const int tid = threadIdx.x, wid = tid >> 5, lane = tid & 31;
    const int m0 = blockIdx.y * 128, n0 = blockIdx.x * 128;
    const int wm = wid & 1, wn = wid >> 1;
    const int mode = (modeArg < 0) ? (int)blockIdx.z : modeArg;

    const __half* Ah = (mode == 3) ? g_ATh : g_Xh;
    const __half* Bh = g_Wh[mode];
    const __half* Bl = g_Wl[mode];

    float acc[4][4][4];
#pragma unroll
    for (int mt = 0; mt < 4; mt++)
#pragma unroll
        for (int nt = 0; nt < 4; nt++)
#pragma unroll
            for (int e = 0; e < 4; e++) acc[mt][nt][e] = 0.f;

#define ISSUE(cc, buf) do {                                                        \
    const int k0_ = (cc) * 32;                                                     \
    const uint32_t s0_ = sb + (buf) * STAGE;                                       \
    _Pragma("unroll")                                                              \
    for (int u = 0; u < 2; u++) {                                                  \
        const int idx = tid + 256 * u;                                             \
        const int r = idx >> 2, c16 = idx & 3;                                     \
        const uint32_t doff = r * SROW + c16 * 16;                                 \
        const size_t aoff = (size_t)(m0 + r) * HID + k0_ + c16 * 8;                \
        const size_t boff = (size_t)(n0 + r) * HID + k0_ + c16 * 8;                \
        CP_ASYNC16(s0_ + doff,           (const char*)&Ah[aoff]);                  \
        CP_ASYNC16(s0_ + TILE_SM + doff, (const char*)&Bh[boff]);                  \
        if (mode != 3)                                                             \
            CP_ASYNC16(s0_ + 2 * TILE_SM + doff, (const char*)&Bl[boff]);          \
    }                                                                              \
    CP_COMMIT();                                                                   \
} while (0)

    ISSUE(0, 0);
    ISSUE(1, 1);
    for (int c = 0; c < 64; c++) {
        const int buf = c % 3;
        if (c < 62) {
            ISSUE(c + 2, (c + 2) % 3);
            asm volatile("cp.async.wait_group 2;" ::: "memory");
        } else if (c == 62) {
            asm volatile("cp.async.wait_group 1;" ::: "memory");
        } else {
            asm volatile("cp.async.wait_group 0;" ::: "memory");
        }
        __syncthreads();

        const uint32_t s0 = sb + buf * STAGE;
        const int kb2 = ((lane >> 4) * 8) * 2;
        const int ar = wm * 64 + (lane & 15);
        const int br = wn * 32 + (lane & 15);
#pragma unroll
        for (int ks = 0; ks < 2; ks++) {
            const int kbyte = ks * 32 + kb2;
            uint32_t ah[4][4];
#pragma unroll
            for (int mt = 0; mt < 4; mt++)
                ldsm4(ah[mt], s0 + (ar + mt * 16) * SROW + kbyte);
            uint32_t bh[2][4];
#pragma unroll
            for (int bt = 0; bt < 2; bt++)
                ldsm4(bh[bt], s0 + TILE_SM + (br + bt * 16) * SROW + kbyte);
#pragma unroll
            for (int mt = 0; mt < 4; mt++)
#pragma unroll
                for (int nt = 0; nt < 4; nt++) {
                    const int bt = nt >> 1, sel = nt & 1;
                    mma_f16(acc[mt][nt], ah[mt], bh[bt][sel], bh[bt][sel + 2]);
                }
            if (mode != 3) {
                uint32_t bl[2][4];
#pragma unroll
                for (int bt = 0; bt < 2; bt++)
                    ldsm4(bl[bt], s0 + 2 * TILE_SM + (br + bt * 16) * SROW + kbyte);
#pragma unroll
                for (int mt = 0; mt < 4; mt++)
#pragma unroll
                    for (int nt = 0; nt < 4; nt++) {
                        const int bt = nt >> 1, sel = nt & 1;
                        mma_f16(acc[mt][nt], ah[mt], bl[bt][sel], bl[bt][sel + 2]);
                    }
            }
        }
        __syncthreads();
    }

    // ---- epilogue via smem tile ----
    float* Cs = (float*)sm8;   // 128 x 132
#pragma unroll
    for (int mt = 0; mt < 4; mt++)
#pragma unroll
        for (int nt = 0; nt < 4; nt++) {
            const int r = wm * 64 + mt * 16 + (lane >> 2);
            const int col = wn * 32 + nt * 8 + (lane & 3) * 2;
            Cs[r * 132 + col]           = acc[mt][nt][0];
            Cs[r * 132 + col + 1]       = acc[mt][nt][1];
            Cs[(r + 8) * 132 + col]     = acc[mt][nt][2];
            Cs[(r + 8) * 132 + col + 1] = acc[mt][nt][3];
        }
    __syncthreads();

    const int h = blockIdx.x;
    if (mode <= 1) {
        for (int p = tid; p < 128 * 64; p += 256) {
            const int r = p >> 6, d = p & 63;
            const float v1 = Cs[r * 132 + d];
            const float v2 = Cs[r * 132 + d + 64];
            const int s_ = m0 + r;
            const float invf = expf(-0.14391156831212788f * (float)d);
            const float ang = (float)s_ * invf;
            float sn, cs;
            sincosf(ang, &sn, &cs);
            const float o1 = v1 * cs - v2 * sn;
            const float o2 = v2 * cs + v1 * sn;
            const size_t base = ((size_t)h * S + s_) * HD;
            if (mode == 0) {
                g_Qh[base + d]      = __float2half_rn(o1);
                g_Qh[base + d + 64] = __float2half_rn(o2);
            } else {
                __half h1 = __float2half_rn(o1);
                __half h2 = __float2half_rn(o2);
                g_Kh[base + d]      = h1;
                g_Kh[base + d + 64] = h2;
                g_Kl[base + d]      = __float2half_rn(o1 - __half2float(h1));
                g_Kl[base + d + 64] = __float2half_rn(o2 - __half2float(h2));
            }
        }
    } else if (mode == 2) {
        const int d = tid >> 1, seg = tid & 1;
        const size_t base = ((size_t)h * HD + d) * S + m0 + seg * 64;
#pragma unroll
        for (int rr = 0; rr < 16; rr++) {
            ushort4 hv, lv;
            float v0 = Cs[(seg * 64 + rr * 4 + 0) * 132 + d];
            float v1 = Cs[(seg * 64 + rr * 4 + 1) * 132 + d];
            float v2 = Cs[(seg * 64 + rr * 4 + 2) * 132 + d];
            float v3 = Cs[(seg * 64 + rr * 4 + 3) * 132 + d];
            __half h0 = __float2half_rn(v0), h1b = __float2half_rn(v1);
            __half h2b = __float2half_rn(v2), h3 = __float2half_rn(v3);
            hv.x = __half_as_ushort(h0); hv.y = __half_as_ushort(h1b);
            hv.z = __half_as_ushort(h2b); hv.w = __half_as_ushort(h3);
            lv.x = __half_as_ushort(__float2half_rn(v0 - __half2float(h0)));
            lv.y = __half_as_ushort(__float2half_rn(v1 - __half2float(h1b)));
            lv.z = __half_as_ushort(__float2half_rn(v2 - __half2float(h2b)));
            lv.w = __half_as_ushort(__float2half_rn(v3 - __half2float(h3)));
            *(ushort4*)&g_Vth[base + rr * 4] = hv;
            *(ushort4*)&g_Vtl[base + rr * 4] = lv;
        }
    } else {
        for (int p = tid; p < 128 * 32; p += 256) {
            const int r = p >> 5, c4 = p & 31;
            float4 v = *(float4*)&Cs[r * 132 + c4 * 4];
            *(float4*)&Cext[(size_t)(m0 + r) * HID + n0 + c4 * 4] = v;
        }
    }
}

// ---------------- aux kernels ----------------
__global__ void masklist_kernel(const float* __restrict__ sp) {
    __shared__ float v[1024];
    __shared__ int msk[1024];
    const int h = blockIdx.x, t = threadIdx.x;
    v[t] = sp[h * 1024 + t];
    __syncthreads();
    const float mine = v[t];
    int cnt = 0;
    for (int i = 0; i < 1024; i++) cnt += (v[i] >= mine);
    msk[t] = (cnt <= KSEL) ? 1 : 0;
    __syncthreads();
    if (t < NQB) {
        const int qb = t;
        int c = 0;
        for (int kb = 0; kb < NKB; kb++)
            if (msk[qb * NKB + kb]) g_list[(h * NQB + qb) * NKB + c++] = kb;
        g_cnt[h * NQB + qb] = c;
    }
}

__global__ void vblk_kernel() {
    const int kb = blockIdx.x, h = blockIdx.y, d = threadIdx.x;
    const size_t base = ((size_t)h * HD + d) * S + kb * 64;
    float s = 0.f;
#pragma unroll 8
    for (int r = 0; r < 64; r++)
        s += __half2float(g_Vth[base + r]) + __half2float(g_Vtl[base + r]);
    g_Vblk[((size_t)h * NKB + kb) * HD + d] = s;
}
__global__ void vtot_kernel() {
    const int h = blockIdx.x, d = threadIdx.x;
    float s = 0.f;
    for (int kb = 0; kb < NKB; kb++) s += g_Vblk[((size_t)h * NKB + kb) * HD + d];
    g_Vtot[h * HD + d] = s;
}

// ---------------- mma.sync block-sparse attention (fp16, 2-chain) ----------------
#define QSTR 272
#define VSTR 144
#define AQ  0
#define AKH 17408
#define AKL 34816
#define AVH 52224
#define AVL 70656
#define ASM_SMALL 89088
#define SMEM_ATTN (ASM_SMALL + 64 * 4 + 128 * 4 + 32 * 4)

__global__ __launch_bounds__(128) void attn_mma() {
    extern __shared__ char smb[];
    const uint32_t sb = smem_u32(smb);
    float* lsum  = (float*)(smb + ASM_SMALL);
    float* vcorr = lsum + 64;
    int*   slist = (int*)(vcorr + 128);

    const int qb = blockIdx.x, h = blockIdx.y;
    const int tid = threadIdx.x, wm = tid >> 5, lane = tid & 31;
    const int lrow = lane & 15, lcb = (lane >> 4) << 4;

    const int cnt = g_cnt[h * NQB + qb];
    if (tid < 32) slist[tid] = g_list[(h * NQB + qb) * NKB + tid];

    {
        const size_t gq = ((size_t)h * S + qb * 64) * HD;
#pragma unroll
        for (int u = 0; u < 8; u++) {
            const int idx = tid + 128 * u;
            const int r = idx >> 4, c = idx & 15;
            CP_ASYNC16(sb + AQ + r * QSTR + c * 16, (const char*)&g_Qh[gq + (size_t)r * HD + c * 8]);
        }
        CP_COMMIT();
    }
    __syncthreads();

    {
        float vc = g_Vtot[h * HD + tid];
        for (int ii = 0; ii < cnt; ii++)
            vc -= g_Vblk[((size_t)h * NKB + slist[ii]) * HD + tid];
        vcorr[tid] = vc * EXPC;
        if (tid < 64) lsum[tid] = (float)(S - 64 * cnt) * EXPC;
    }
    __syncthreads();

    float oacc[16][4];
#pragma unroll
    for (int i = 0; i < 16; i++)
#pragma unroll
        for (int e = 0; e < 4; e++) oacc[i][e] = 0.f;

    for (int ii = 0; ii < cnt; ii++) {
        const int kb = slist[ii];
        const size_t gk = ((size_t)h * S + kb * 64) * HD;
        const size_t gv = (size_t)h * HD * S + (size_t)kb * 64;
#pragma unroll
        for (int u = 0; u < 8; u++) {
            const int idx = tid + 128 * u;
            const int r = idx >> 4, c = idx & 15;
            CP_ASYNC16(sb + AKH + r * QSTR + c * 16, (const char*)&g_Kh[gk + (size_t)r * HD + c * 8]);
            CP_ASYNC16(sb + AKL + r * QSTR + c * 16, (const char*)&g_Kl[gk + (size_t)r * HD + c * 8]);
            const int rv = idx >> 3, cv = idx & 7;
            CP_ASYNC16(sb + AVH + rv * VSTR + cv * 16, (const char*)&g_Vth[gv + (size_t)rv * S + cv * 8]);
            CP_ASYNC16(sb + AVL + rv * VSTR + cv * 16, (const char*)&g_Vtl[gv + (size_t)rv * S + cv * 8]);
        }
        CP_COMMIT();
        asm volatile("cp.async.wait_group 0;" ::: "memory");
        __syncthreads();

        float sacc[8][4];
#pragma unroll
        for (int i = 0; i < 8; i++)
#pragma unroll
            for (int e = 0; e < 4; e++) sacc[i][e] = 0.f;
#pragma unroll
        for (int kt = 0; kt < 8; kt++) {
            uint32_t qh[4];
            ldsm4(qh, sb + AQ + (wm * 16 + lrow) * QSTR + kt * 32 + lcb);
#pragma unroll
            for (int jt = 0; jt < 4; jt++) {
                uint32_t kh[4], kl[4];
                const uint32_t ka = sb + AKH + (jt * 16 + lrow) * QSTR + kt * 32 + lcb;
                ldsm4(kh, ka);
                ldsm4(kl, ka + (AKL - AKH));
                mma_f16(sacc[2 * jt],     qh, kh[0], kh[2]);
                mma_f16(sacc[2 * jt + 1], qh, kh[1], kh[3]);
                mma_f16(sacc[2 * jt],     qh, kl[0], kl[2]);
                mma_f16(sacc[2 * jt + 1], qh, kl[1], kl[3]);
            }
        }

        uint32_t pah[4][4];
        float rs0 = 0.f, rs1 = 0.f;
#pragma unroll
        for (int nt = 0; nt < 8; nt++) {
            const float p0 = __expf(fmaf(sacc[nt][0], SCALE, -ESHIFT));
            const float p1 = __expf(fmaf(sacc[nt][1], SCALE, -ESHIFT));
            const float p2 = __expf(fmaf(sacc[nt][2], SCALE, -ESHIFT));
            const float p3 = __expf(fmaf(sacc[nt][3], SCALE, -ESHIFT));
            rs0 += p0 + p1;
            rs1 += p2 + p3;
            const int g = nt >> 1, o = (nt & 1) * 2;
            pah[g][o]     = packh2(p0, p1);
            pah[g][o + 1] = packh2(p2, p3);
        }
        rs0 += __shfl_xor_sync(0xffffffffu, rs0, 1);
        rs0 += __shfl_xor_sync(0xffffffffu, rs0, 2);
        rs1 += __shfl_xor_sync(0xffffffffu, rs1, 1);
        rs1 += __shfl_xor_sync(0xffffffffu, rs1, 2);
        if ((lane & 3) == 0) {
            lsum[wm * 16 + (lane >> 2)]     += rs0;
            lsum[wm * 16 + (lane >> 2) + 8] += rs1;
        }

#pragma unroll
        for (int g = 0; g < 4; g++) {
#pragma unroll
            for (int dt = 0; dt < 8; dt++) {
                uint32_t vh[4], vl[4];
                const uint32_t va = sb + AVH + (dt * 16 + lrow) * VSTR + g * 32 + lcb;
                ldsm4(vh, va);
                ldsm4(vl, va + (AVL - AVH));
                mma_f16(oacc[2 * dt],     pah[g], vh[0], vh[2]);
                mma_f16(oacc[2 * dt + 1], pah[g], vh[1], vh[3]);
                mma_f16(oacc[2 * dt],     pah[g], vl[0], vl[2]);
                mma_f16(oacc[2 * dt + 1], pah[g], vl[1], vl[3]);
            }
        }
        __syncthreads();
    }
    asm volatile("cp.async.wait_group 0;" ::: "memory");
    __syncthreads();

    const int r0 = wm * 16 + (lane >> 2);
    const float il0 = 1.f / lsum[r0];
    const float il1 = 1.f / lsum[r0 + 8];
    const int cbase = 2 * (lane & 3);
    const size_t ob0 = (size_t)(qb * 64 + r0) * HID + h * HD;
    const size_t ob1 = ob0 + (size_t)8 * HID;
#pragma unroll
    for (int ot = 0; ot < 16; ot++) {
        const int c = 8 * ot + cbase;
        const float a0 = (oacc[ot][0] + vcorr[c]) * il0;
        const float a1 = (oacc[ot][1] + vcorr[c + 1]) * il0;
        const float b0 = (oacc[ot][2] + vcorr[c]) * il1;
        const float b1 = (oacc[ot][3] + vcorr[c + 1]) * il1;
        ((uint32_t*)g_ATh)[(ob0 + c) >> 1] = packh2(a0, a1);
        ((uint32_t*)g_ATh)[(ob1 + c) >> 1] = packh2(b0, b1);
    }
}

// ---------------------------------------------------------------------------
extern "C" void kernel_launch(void* const* d_in, const int* in_sizes, int n_in,
                              void* d_out, int out_size) {
    const float* X  = (const float*)d_in[0];
    const float* qw = (const float*)d_in[1];
    const float* kw = (const float*)d_in[2];
    const float* vw = (const float*)d_in[3];
    const float* ow = (const float*)d_in[4];
    const float* sp = (const float*)d_in[5];
    float* out = (float*)d_out;

    cudaFuncSetAttribute(mma_gemm, cudaFuncAttributeMaxDynamicSharedMemorySize, GEMM_SMEM);
    cudaFuncSetAttribute(attn_mma, cudaFuncAttributeMaxDynamicSharedMemorySize, SMEM_ATTN);

    convert_h<<<(S * HID / 4 + 255) / 256, 256>>>(X);
    convert_T4<<<dim3(64, 64, 4), dim3(32, 8)>>>(qw, kw, vw, ow);
    mma_gemm<<<dim3(16, 16, 3), 256, GEMM_SMEM>>>(nullptr, -1);
    masklist_kernel<<<NH, 1024>>>(sp);
    vblk_kernel<<<dim3(NKB, NH), HD>>>();
    vtot_kernel<<<NH, HD>>>();
    attn_mma<<<dim3(NQB, NH), 128, SMEM_ATTN>>>();
    mma_gemm<<<dim3(16, 16), 256, GEMM_SMEM>>>(out, 3);
}

// round 13
// speedup vs baseline: 2.2100x; 1.4916x over previous
#include <cuda_runtime.h>
#include <cuda_fp16.h>
#include <math.h>
#include <stdint.h>

// Problem constants
#define S     2048
#define HID   2048
#define NH    16
#define HD    128
#define BS_   64
#define NQB   32
#define NKB   32
#define KSEL  511
#define SCALE 0.08838834764831845f
#define ESHIFT 4.0f
#define EXPC  0.01831563889f   // e^-4

// ---------------- device scratch (allocation-free) ----------------
__device__ float g_Vblk[NH * NKB * HD];
__device__ float g_Vtot[NH * HD];
__device__ int   g_list[NH * NQB * NKB];
__device__ int   g_cnt[NH * NQB];

// plain fp16 operands everywhere
__device__ __half g_Xh[S * HID];
__device__ __half g_Wh[4][HID * HID];
__device__ __half g_ATh[S * HID];

__device__ __half g_Qh[NH * S * HD];
__device__ __half g_Kh[NH * S * HD];
__device__ __half g_Vth[NH * HD * S];    // [h][d][s]

// ---------------- helpers ----------------
__device__ __forceinline__ uint32_t smem_u32(const void* p) {
    uint32_t a;
    asm("{ .reg .u64 t; cvta.to.shared.u64 t, %1; cvt.u32.u64 %0, t; }" : "=r"(a) : "l"(p));
    return a;
}
__device__ __forceinline__ void ldsm4(uint32_t (&r)[4], uint32_t addr) {
    asm volatile("ldmatrix.sync.aligned.m8n8.x4.shared.b16 {%0,%1,%2,%3}, [%4];"
        : "=r"(r[0]), "=r"(r[1]), "=r"(r[2]), "=r"(r[3]) : "r"(addr));
}
__device__ __forceinline__ void mma_f16(float (&d)[4], const uint32_t (&a)[4],
                                        uint32_t b0, uint32_t b1) {
    asm volatile("mma.sync.aligned.m16n8k16.row.col.f32.f16.f16.f32 "
        "{%0,%1,%2,%3}, {%4,%5,%6,%7}, {%8,%9}, {%0,%1,%2,%3};"
        : "+f"(d[0]), "+f"(d[1]), "+f"(d[2]), "+f"(d[3])
        : "r"(a[0]), "r"(a[1]), "r"(a[2]), "r"(a[3]), "r"(b0), "r"(b1));
}
#define CP_ASYNC16(dst, src) \
    asm volatile("cp.async.cg.shared.global [%0], [%1], 16;" :: "r"(dst), "l"(src))
#define CP_COMMIT() asm volatile("cp.async.commit_group;" ::: "memory")

__device__ __forceinline__ uint32_t packh2(float a, float b) {
    __half2 h = __floats2half2_rn(a, b);
    return *reinterpret_cast<uint32_t*>(&h);
}

// ---------------- conversions ----------------
__global__ void convert_h(const float* __restrict__ src) {
    int i = blockIdx.x * blockDim.x + threadIdx.x;
    float4 v = ((const float4*)src)[i];
    ushort4 hv = { __half_as_ushort(__float2half_rn(v.x)),
                   __half_as_ushort(__float2half_rn(v.y)),
                   __half_as_ushort(__float2half_rn(v.z)),
                   __half_as_ushort(__float2half_rn(v.w)) };
    ((ushort4*)g_Xh)[i] = hv;
}

__global__ void convert_T4(const float* __restrict__ qw, const float* __restrict__ kw,
                           const float* __restrict__ vw, const float* __restrict__ ow) {
    __shared__ float t[32][33];
    const int widx = blockIdx.z;
    const float* W = (widx == 0) ? qw : (widx == 1) ? kw : (widx == 2) ? vw : ow;
    const int k0 = blockIdx.y * 32, n0 = blockIdx.x * 32;
    const int tx = threadIdx.x, ty = threadIdx.y;
#pragma unroll
    for (int j = 0; j < 4; j++)
        t[ty + 8 * j][tx] = W[(size_t)(k0 + ty + 8 * j) * HID + n0 + tx];
    __syncthreads();
#pragma unroll
    for (int j = 0; j < 4; j++) {
        const int n = n0 + ty + 8 * j, k = k0 + tx;
        g_Wh[widx][(size_t)n * HID + k] = __float2half_rn(t[tx][ty + 8 * j]);
    }
}

// ---------------- mma.sync fp16 single-chain GEMM, 3-stage ----------------
#define SROW    80
#define TILE_SM (128 * SROW)        // 10240
#define STAGE   (2 * TILE_SM)       // 20480 (A + B)
#define GEMM_SMEM 67584             // max(3*STAGE=61440, epilogue 128*132*4)

__global__ __launch_bounds__(256) void mma_gemm(float* __restrict__ Cext, int modeArg) {
    extern __shared__ char sm8[];
    const uint32_t sb = smem_u32(sm8);
    const int tid = threadIdx.x, wid = tid >> 5, lane = tid & 31;
    const int m0 = blockIdx.y * 128, n0 = blockIdx.x * 128;
    const int wm = wid & 1, wn = wid >> 1;
    const int mode = (modeArg < 0) ? (int)blockIdx.z : modeArg;

    const __half* Ah = (mode == 3) ? g_ATh : g_Xh;
    const __half* Bh = g_Wh[mode];

    float acc[4][4][4];
#pragma unroll
    for (int mt = 0; mt < 4; mt++)
#pragma unroll
        for (int nt = 0; nt < 4; nt++)
#pragma unroll
            for (int e = 0; e < 4; e++) acc[mt][nt][e] = 0.f;

#define ISSUE(cc, buf) do {                                                        \
    const int k0_ = (cc) * 32;                                                     \
    const uint32_t s0_ = sb + (buf) * STAGE;                                       \
    _Pragma("unroll")                                                              \
    for (int u = 0; u < 2; u++) {                                                  \
        const int idx = tid + 256 * u;                                             \
        const int r = idx >> 2, c16 = idx & 3;                                     \
        const uint32_t doff = r * SROW + c16 * 16;                                 \
        CP_ASYNC16(s0_ + doff,           (const char*)&Ah[(size_t)(m0 + r) * HID + k0_ + c16 * 8]); \
        CP_ASYNC16(s0_ + TILE_SM + doff, (const char*)&Bh[(size_t)(n0 + r) * HID + k0_ + c16 * 8]); \
    }                                                                              \
    CP_COMMIT();                                                                   \
} while (0)

    ISSUE(0, 0);
    ISSUE(1, 1);
    for (int c = 0; c < 64; c++) {
        const int buf = c % 3;
        if (c < 62) {
            ISSUE(c + 2, (c + 2) % 3);
            asm volatile("cp.async.wait_group 2;" ::: "memory");
        } else if (c == 62) {
            asm volatile("cp.async.wait_group 1;" ::: "memory");
        } else {
            asm volatile("cp.async.wait_group 0;" ::: "memory");
        }
        __syncthreads();

        const uint32_t s0 = sb + buf * STAGE;
        const int kb2 = ((lane >> 4) * 8) * 2;
        const int ar = wm * 64 + (lane & 15);
        const int br = wn * 32 + (lane & 15);
#pragma unroll
        for (int ks = 0; ks < 2; ks++) {
            const int kbyte = ks * 32 + kb2;
            uint32_t ah[4][4];
#pragma unroll
            for (int mt = 0; mt < 4; mt++)
                ldsm4(ah[mt], s0 + (ar + mt * 16) * SROW + kbyte);
            uint32_t bh[2][4];
#pragma unroll
            for (int bt = 0; bt < 2; bt++)
                ldsm4(bh[bt], s0 + TILE_SM + (br + bt * 16) * SROW + kbyte);
#pragma unroll
            for (int mt = 0; mt < 4; mt++)
#pragma unroll
                for (int nt = 0; nt < 4; nt++) {
                    const int bt = nt >> 1, sel = nt & 1;
                    mma_f16(acc[mt][nt], ah[mt], bh[bt][sel], bh[bt][sel + 2]);
                }
        }
        __syncthreads();
    }

    // ---- epilogue via smem tile ----
    float* Cs = (float*)sm8;   // 128 x 132
#pragma unroll
    for (int mt = 0; mt < 4; mt++)
#pragma unroll
        for (int nt = 0; nt < 4; nt++) {
            const int r = wm * 64 + mt * 16 + (lane >> 2);
            const int col = wn * 32 + nt * 8 + (lane & 3) * 2;
            Cs[r * 132 + col]           = acc[mt][nt][0];
            Cs[r * 132 + col + 1]       = acc[mt][nt][1];
            Cs[(r + 8) * 132 + col]     = acc[mt][nt][2];
            Cs[(r + 8) * 132 + col + 1] = acc[mt][nt][3];
        }
    __syncthreads();

    const int h = blockIdx.x;
    if (mode <= 1) {
        __half* G = mode ? g_Kh : g_Qh;
        for (int p = tid; p < 128 * 64; p += 256) {
            const int r = p >> 6, d = p & 63;
            const float v1 = Cs[r * 132 + d];
            const float v2 = Cs[r * 132 + d + 64];
            const int s_ = m0 + r;
            const float invf = expf(-0.14391156831212788f * (float)d);
            const float ang = (float)s_ * invf;
            float sn, cs;
            sincosf(ang, &sn, &cs);
            const size_t base = ((size_t)h * S + s_) * HD;
            G[base + d]      = __float2half_rn(v1 * cs - v2 * sn);
            G[base + d + 64] = __float2half_rn(v2 * cs + v1 * sn);
        }
    } else if (mode == 2) {
        const int d = tid >> 1, seg = tid & 1;
        const size_t base = ((size_t)h * HD + d) * S + m0 + seg * 64;
#pragma unroll
        for (int rr = 0; rr < 16; rr++) {
            ushort4 hv;
            hv.x = __half_as_ushort(__float2half_rn(Cs[(seg * 64 + rr * 4 + 0) * 132 + d]));
            hv.y = __half_as_ushort(__float2half_rn(Cs[(seg * 64 + rr * 4 + 1) * 132 + d]));
            hv.z = __half_as_ushort(__float2half_rn(Cs[(seg * 64 + rr * 4 + 2) * 132 + d]));
            hv.w = __half_as_ushort(__float2half_rn(Cs[(seg * 64 + rr * 4 + 3) * 132 + d]));
            *(ushort4*)&g_Vth[base + rr * 4] = hv;
        }
    } else {
        for (int p = tid; p < 128 * 32; p += 256) {
            const int r = p >> 5, c4 = p & 31;
            float4 v = *(float4*)&Cs[r * 132 + c4 * 4];
            *(float4*)&Cext[(size_t)(m0 + r) * HID + n0 + c4 * 4] = v;
        }
    }
}

// ---------------- aux kernels ----------------
__global__ void masklist_kernel(const float* __restrict__ sp) {
    __shared__ float v[1024];
    __shared__ int msk[1024];
    const int h = blockIdx.x, t = threadIdx.x;
    v[t] = sp[h * 1024 + t];
    __syncthreads();
    const float mine = v[t];
    int cnt = 0;
    for (int i = 0; i < 1024; i++) cnt += (v[i] >= mine);
    msk[t] = (cnt <= KSEL) ? 1 : 0;
    __syncthreads();
    if (t < NQB) {
        const int qb = t;
        int c = 0;
        for (int kb = 0; kb < NKB; kb++)
            if (msk[qb * NKB + kb]) g_list[(h * NQB + qb) * NKB + c++] = kb;
        g_cnt[h * NQB + qb] = c;
    }
}

__global__ void vblk_kernel() {
    const int kb = blockIdx.x, h = blockIdx.y, d = threadIdx.x;
    const size_t base = ((size_t)h * HD + d) * S + kb * 64;
    float s = 0.f;
#pragma unroll 8
    for (int r = 0; r < 64; r++) s += __half2float(g_Vth[base + r]);
    g_Vblk[((size_t)h * NKB + kb) * HD + d] = s;
}
__global__ void vtot_kernel() {
    const int h = blockIdx.x, d = threadIdx.x;
    float s = 0.f;
    for (int kb = 0; kb < NKB; kb++) s += g_Vblk[((size_t)h * NKB + kb) * HD + d];
    g_Vtot[h * HD + d] = s;
}

// ---------------- mma.sync block-sparse attention (fp16 1-chain, K/V double buffered) ----------------
#define QSTR 272
#define VSTR 144
#define AQ   0
#define KVST 35840                 // per-buffer: K 17408 + V 18432
#define AK(b) (17408 + (b) * KVST)
#define AV(b) (AK(b) + 17408)
#define ASM_SMALL (17408 + 2 * KVST)   // 89088
#define SMEM_ATTN (ASM_SMALL + 64 * 4 + 128 * 4 + 32 * 4)

__global__ __launch_bounds__(128) void attn_mma() {
    extern __shared__ char smb[];
    const uint32_t sb = smem_u32(smb);
    float* lsum  = (float*)(smb + ASM_SMALL);
    float* vcorr = lsum + 64;
    int*   slist = (int*)(vcorr + 128);

    const int qb = blockIdx.x, h = blockIdx.y;
    const int tid = threadIdx.x, wm = tid >> 5, lane = tid & 31;
    const int lrow = lane & 15, lcb = (lane >> 4) << 4;

    const int cnt = g_cnt[h * NQB + qb];
    if (tid < 32) slist[tid] = g_list[(h * NQB + qb) * NKB + tid];

    // Q load (group 0)
    {
        const size_t gq = ((size_t)h * S + qb * 64) * HD;
#pragma unroll
        for (int u = 0; u < 8; u++) {
            const int idx = tid + 128 * u;
            const int r = idx >> 4, c = idx & 15;
            CP_ASYNC16(sb + AQ + r * QSTR + c * 16, (const char*)&g_Qh[gq + (size_t)r * HD + c * 8]);
        }
        CP_COMMIT();
    }
    __syncthreads();   // slist visible

#define ISSUE_KV(ii, buf) do {                                                      \
    const int kb_ = slist[ii];                                                      \
    const size_t gk_ = ((size_t)h * S + kb_ * 64) * HD;                             \
    const size_t gv_ = (size_t)h * HD * S + (size_t)kb_ * 64;                       \
    _Pragma("unroll")                                                               \
    for (int u = 0; u < 8; u++) {                                                   \
        const int idx = tid + 128 * u;                                              \
        const int r = idx >> 4, c = idx & 15;                                       \
        CP_ASYNC16(sb + AK(buf) + r * QSTR + c * 16, (const char*)&g_Kh[gk_ + (size_t)r * HD + c * 8]); \
        const int rv = idx >> 3, cv = idx & 7;                                      \
        CP_ASYNC16(sb + AV(buf) + rv * VSTR + cv * 16, (const char*)&g_Vth[gv_ + (size_t)rv * S + cv * 8]); \
    }                                                                               \
    CP_COMMIT();                                                                    \
} while (0)

    if (cnt > 0) ISSUE_KV(0, 0);

    {
        float vc = g_Vtot[h * HD + tid];
        for (int ii = 0; ii < cnt; ii++)
            vc -= g_Vblk[((size_t)h * NKB + slist[ii]) * HD + tid];
        vcorr[tid] = vc * EXPC;
        if (tid < 64) lsum[tid] = (float)(S - 64 * cnt) * EXPC;
    }
    __syncthreads();

    float oacc[16][4];
#pragma unroll
    for (int i = 0; i < 16; i++)
#pragma unroll
        for (int e = 0; e < 4; e++) oacc[i][e] = 0.f;

    for (int ii = 0; ii < cnt; ii++) {
        const int buf = ii & 1;
        if (ii + 1 < cnt) {
            ISSUE_KV(ii + 1, buf ^ 1);
            asm volatile("cp.async.wait_group 1;" ::: "memory");
        } else {
            asm volatile("cp.async.wait_group 0;" ::: "memory");
        }
        __syncthreads();

        // S = Q K^T (single chain)
        float sacc[8][4];
#pragma unroll
        for (int i = 0; i < 8; i++)
#pragma unroll
            for (int e = 0; e < 4; e++) sacc[i][e] = 0.f;
#pragma unroll
        for (int kt = 0; kt < 8; kt++) {
            uint32_t qh[4];
            ldsm4(qh, sb + AQ + (wm * 16 + lrow) * QSTR + kt * 32 + lcb);
#pragma unroll
            for (int jt = 0; jt < 4; jt++) {
                uint32_t kh[4];
                ldsm4(kh, sb + AK(buf) + (jt * 16 + lrow) * QSTR + kt * 32 + lcb);
                mma_f16(sacc[2 * jt],     qh, kh[0], kh[2]);
                mma_f16(sacc[2 * jt + 1], qh, kh[1], kh[3]);
            }
        }

        uint32_t pah[4][4];
        float rs0 = 0.f, rs1 = 0.f;
#pragma unroll
        for (int nt = 0; nt < 8; nt++) {
            const float p0 = __expf(fmaf(sacc[nt][0], SCALE, -ESHIFT));
            const float p1 = __expf(fmaf(sacc[nt][1], SCALE, -ESHIFT));
            const float p2 = __expf(fmaf(sacc[nt][2], SCALE, -ESHIFT));
            const float p3 = __expf(fmaf(sacc[nt][3], SCALE, -ESHIFT));
            rs0 += p0 + p1;
            rs1 += p2 + p3;
            const int g = nt >> 1, o = (nt & 1) * 2;
            pah[g][o]     = packh2(p0, p1);
            pah[g][o + 1] = packh2(p2, p3);
        }
        rs0 += __shfl_xor_sync(0xffffffffu, rs0, 1);
        rs0 += __shfl_xor_sync(0xffffffffu, rs0, 2);
        rs1 += __shfl_xor_sync(0xffffffffu, rs1, 1);
        rs1 += __shfl_xor_sync(0xffffffffu, rs1, 2);
        if ((lane & 3) == 0) {
            lsum[wm * 16 + (lane >> 2)]     += rs0;
            lsum[wm * 16 + (lane >> 2) + 8] += rs1;
        }

        // O += P V (single chain)
#pragma unroll
        for (int g = 0; g < 4; g++) {
#pragma unroll
            for (int dt = 0; dt < 8; dt++) {
                uint32_t vh[4];
                ldsm4(vh, sb + AV(buf) + (dt * 16 + lrow) * VSTR + g * 32 + lcb);
                mma_f16(oacc[2 * dt],     pah[g], vh[0], vh[2]);
                mma_f16(oacc[2 * dt + 1], pah[g], vh[1], vh[3]);
            }
        }
        __syncthreads();
    }
    asm volatile("cp.async.wait_group 0;" ::: "memory");
    __syncthreads();

    const int r0 = wm * 16 + (lane >> 2);
    const float il0 = 1.f / lsum[r0];
    const float il1 = 1.f / lsum[r0 + 8];
    const int cbase = 2 * (lane & 3);
    const size_t ob0 = (size_t)(qb * 64 + r0) * HID + h * HD;
    const size_t ob1 = ob0 + (size_t)8 * HID;
#pragma unroll
    for (int ot = 0; ot < 16; ot++) {
        const int c = 8 * ot + cbase;
        const float a0 = (oacc[ot][0] + vcorr[c]) * il0;
        const float a1 = (oacc[ot][1] + vcorr[c + 1]) * il0;
        const float b0 = (oacc[ot][2] + vcorr[c]) * il1;
        const float b1 = (oacc[ot][3] + vcorr[c + 1]) * il1;
        ((uint32_t*)g_ATh)[(ob0 + c) >> 1] = packh2(a0, a1);
        ((uint32_t*)g_ATh)[(ob1 + c) >> 1] = packh2(b0, b1);
    }
}

// ---------------------------------------------------------------------------
extern "C" void kernel_launch(void* const* d_in, const int* in_sizes, int n_in,
                              void* d_out, int out_size) {
    const float* X  = (const float*)d_in[0];
    const float* qw = (const float*)d_in[1];
    const float* kw = (const float*)d_in[2];
    const float* vw = (const float*)d_in[3];
    const float* ow = (const float*)d_in[4];
    const float* sp = (const float*)d_in[5];
    float* out = (float*)d_out;

    cudaFuncSetAttribute(mma_gemm, cudaFuncAttributeMaxDynamicSharedMemorySize, GEMM_SMEM);
    cudaFuncSetAttribute(attn_mma, cudaFuncAttributeMaxDynamicSharedMemorySize, SMEM_ATTN);

    convert_h<<<(S * HID / 4 + 255) / 256, 256>>>(X);
    convert_T4<<<dim3(64, 64, 4), dim3(32, 8)>>>(qw, kw, vw, ow);
    mma_gemm<<<dim3(16, 16, 3), 256, GEMM_SMEM>>>(nullptr, -1);
    masklist_kernel<<<NH, 1024>>>(sp);
    vblk_kernel<<<dim3(NKB, NH), HD>>>();
    vtot_kernel<<<NH, HD>>>();
    attn_mma<<<dim3(NQB, NH), 128, SMEM_ATTN>>>();
    mma_gemm<<<dim3(16, 16), 256, GEMM_SMEM>>>(out, 3);
}

// round 14
// speedup vs baseline: 2.2430x; 1.0149x over previous
#include <cuda_runtime.h>
#include <cuda_fp16.h>
#include <math.h>
#include <stdint.h>

// Problem constants
#define S     2048
#define HID   2048
#define NH    16
#define HD    128
#define BS_   64
#define NQB   32
#define NKB   32
#define KSEL  511
#define SCALE 0.08838834764831845f
#define ESHIFT 4.0f
#define EXPC  0.01831563889f   // e^-4

// ---------------- device scratch (allocation-free) ----------------
__device__ float g_Vblk[NH * NKB * HD];
__device__ float g_Vtot[NH * HD];
__device__ int   g_mask[NH * NQB * NKB];
__device__ int   g_list[NH * NQB * NKB];
__device__ int   g_cnt[NH * NQB];

// plain fp16 operands everywhere
__device__ __half g_Xh[S * HID];
__device__ __half g_Wh[4][HID * HID];
__device__ __half g_ATh[S * HID];

__device__ __half g_Qh[NH * S * HD];
__device__ __half g_Kh[NH * S * HD];
__device__ __half g_Vth[NH * HD * S];    // [h][d][s]

// ---------------- helpers ----------------
__device__ __forceinline__ uint32_t smem_u32(const void* p) {
    uint32_t a;
    asm("{ .reg .u64 t; cvta.to.shared.u64 t, %1; cvt.u32.u64 %0, t; }" : "=r"(a) : "l"(p));
    return a;
}
__device__ __forceinline__ void ldsm4(uint32_t (&r)[4], uint32_t addr) {
    asm volatile("ldmatrix.sync.aligned.m8n8.x4.shared.b16 {%0,%1,%2,%3}, [%4];"
        : "=r"(r[0]), "=r"(r[1]), "=r"(r[2]), "=r"(r[3]) : "r"(addr));
}
__device__ __forceinline__ void mma_f16(float (&d)[4], const uint32_t (&a)[4],
                                        uint32_t b0, uint32_t b1) {
    asm volatile("mma.sync.aligned.m16n8k16.row.col.f32.f16.f16.f32 "
        "{%0,%1,%2,%3}, {%4,%5,%6,%7}, {%8,%9}, {%0,%1,%2,%3};"
        : "+f"(d[0]), "+f"(d[1]), "+f"(d[2]), "+f"(d[3])
        : "r"(a[0]), "r"(a[1]), "r"(a[2]), "r"(a[3]), "r"(b0), "r"(b1));
}
#define CP_ASYNC16(dst, src) \
    asm volatile("cp.async.cg.shared.global [%0], [%1], 16;" :: "r"(dst), "l"(src))
#define CP_COMMIT() asm volatile("cp.async.commit_group;" ::: "memory")

__device__ __forceinline__ uint32_t packh2(float a, float b) {
    __half2 h = __floats2half2_rn(a, b);
    return *reinterpret_cast<uint32_t*>(&h);
}

// ---------------- conversions ----------------
__global__ void convert_h(const float* __restrict__ src) {
    int i = blockIdx.x * blockDim.x + threadIdx.x;
    float4 v = ((const float4*)src)[i];
    ushort4 hv = { __half_as_ushort(__float2half_rn(v.x)),
                   __half_as_ushort(__float2half_rn(v.y)),
                   __half_as_ushort(__float2half_rn(v.z)),
                   __half_as_ushort(__float2half_rn(v.w)) };
    ((ushort4*)g_Xh)[i] = hv;
}

__global__ void convert_T4(const float* __restrict__ qw, const float* __restrict__ kw,
                           const float* __restrict__ vw, const float* __restrict__ ow) {
    __shared__ float t[32][33];
    const int widx = blockIdx.z;
    const float* W = (widx == 0) ? qw : (widx == 1) ? kw : (widx == 2) ? vw : ow;
    const int k0 = blockIdx.y * 32, n0 = blockIdx.x * 32;
    const int tx = threadIdx.x, ty = threadIdx.y;
#pragma unroll
    for (int j = 0; j < 4; j++)
        t[ty + 8 * j][tx] = W[(size_t)(k0 + ty + 8 * j) * HID + n0 + tx];
    __syncthreads();
#pragma unroll
    for (int j = 0; j < 4; j++) {
        const int n = n0 + ty + 8 * j, k = k0 + tx;
        g_Wh[widx][(size_t)n * HID + k] = __float2half_rn(t[tx][ty + 8 * j]);
    }
}

// ---------------- mask (parallel count) + list ----------------
__global__ void mask_kernel(const float* __restrict__ sp) {
    __shared__ float v[1024];
    const int h = blockIdx.x, chunk = blockIdx.y, t = threadIdx.x;  // 256 thr
    for (int i = t; i < 1024; i += 256) v[i] = sp[h * 1024 + i];
    __syncthreads();
    const int idx = chunk * 256 + t;
    const float mine = v[idx];
    int c = 0;
#pragma unroll 8
    for (int i = 0; i < 1024; i++) c += (v[i] >= mine);
    g_mask[h * 1024 + idx] = (c <= KSEL) ? 1 : 0;
}

__global__ void list_kernel() {
    const int t = threadIdx.x;
    if (t >= NH * NQB) return;
    const int h = t / NQB, qb = t % NQB;
    int c = 0;
    for (int kb = 0; kb < NKB; kb++)
        if (g_mask[(h * NQB + qb) * NKB + kb]) g_list[(h * NQB + qb) * NKB + c++] = kb;
    g_cnt[h * NQB + qb] = c;
}

// ---------------- mma.sync fp16 single-chain GEMM, 3-stage ----------------
#define SROW    80
#define TILE_SM (128 * SROW)        // 10240
#define STAGE   (2 * TILE_SM)       // 20480 (A + B)
#define GEMM_SMEM 67584             // max(3*STAGE=61440, epilogue 128*132*4)

__global__ __launch_bounds__(256) void mma_gemm(float* __restrict__ Cext, int modeArg) {
    extern __shared__ char sm8[];
    const uint32_t sb = smem_u32(sm8);
    const int tid = threadIdx.x, wid = tid >> 5, lane = tid & 31;
    const int m0 = blockIdx.y * 128, n0 = blockIdx.x * 128;
    const int wm = wid & 1, wn = wid >> 1;
    const int mode = (modeArg < 0) ? (int)blockIdx.z : modeArg;

    const __half* Ah = (mode == 3) ? g_ATh : g_Xh;
    const __half* Bh = g_Wh[mode];

    float acc[4][4][4];
#pragma unroll
    for (int mt = 0; mt < 4; mt++)
#pragma unroll
        for (int nt = 0; nt < 4; nt++)
#pragma unroll
            for (int e = 0; e < 4; e++) acc[mt][nt][e] = 0.f;

#define ISSUE(cc, buf) do {                                                        \
    const int k0_ = (cc) * 32;                                                     \
    const uint32_t s0_ = sb + (buf) * STAGE;                                       \
    _Pragma("unroll")                                                              \
    for (int u = 0; u < 2; u++) {                                                  \
        const int idx = tid + 256 * u;                                             \
        const int r = idx >> 2, c16 = idx & 3;                                     \
        const uint32_t doff = r * SROW + c16 * 16;                                 \
        CP_ASYNC16(s0_ + doff,           (const char*)&Ah[(size_t)(m0 + r) * HID + k0_ + c16 * 8]); \
        CP_ASYNC16(s0_ + TILE_SM + doff, (const char*)&Bh[(size_t)(n0 + r) * HID + k0_ + c16 * 8]); \
    }                                                                              \
    CP_COMMIT();                                                                   \
} while (0)

    ISSUE(0, 0);
    ISSUE(1, 1);
    for (int c = 0; c < 64; c++) {
        const int buf = c % 3;
        if (c < 62) {
            ISSUE(c + 2, (c + 2) % 3);
            asm volatile("cp.async.wait_group 2;" ::: "memory");
        } else if (c == 62) {
            asm volatile("cp.async.wait_group 1;" ::: "memory");
        } else {
            asm volatile("cp.async.wait_group 0;" ::: "memory");
        }
        __syncthreads();

        const uint32_t s0 = sb + buf * STAGE;
        const int kb2 = ((lane >> 4) * 8) * 2;
        const int ar = wm * 64 + (lane & 15);
        const int br = wn * 32 + (lane & 15);
#pragma unroll
        for (int ks = 0; ks < 2; ks++) {
            const int kbyte = ks * 32 + kb2;
            uint32_t ah[4][4];
#pragma unroll
            for (int mt = 0; mt < 4; mt++)
                ldsm4(ah[mt], s0 + (ar + mt * 16) * SROW + kbyte);
            uint32_t bh[2][4];
#pragma unroll
            for (int bt = 0; bt < 2; bt++)
                ldsm4(bh[bt], s0 + TILE_SM + (br + bt * 16) * SROW + kbyte);
#pragma unroll
            for (int mt = 0; mt < 4; mt++)
#pragma unroll
                for (int nt = 0; nt < 4; nt++) {
                    const int bt = nt >> 1, sel = nt & 1;
                    mma_f16(acc[mt][nt], ah[mt], bh[bt][sel], bh[bt][sel + 2]);
                }
        }
        __syncthreads();
    }

    // ---- epilogue via smem tile ----
    float* Cs = (float*)sm8;   // 128 x 132
#pragma unroll
    for (int mt = 0; mt < 4; mt++)
#pragma unroll
        for (int nt = 0; nt < 4; nt++) {
            const int r = wm * 64 + mt * 16 + (lane >> 2);
            const int col = wn * 32 + nt * 8 + (lane & 3) * 2;
            Cs[r * 132 + col]           = acc[mt][nt][0];
            Cs[r * 132 + col + 1]       = acc[mt][nt][1];
            Cs[(r + 8) * 132 + col]     = acc[mt][nt][2];
            Cs[(r + 8) * 132 + col + 1] = acc[mt][nt][3];
        }
    __syncthreads();

    const int h = blockIdx.x;
    if (mode <= 1) {
        __half* G = mode ? g_Kh : g_Qh;
        for (int p = tid; p < 128 * 64; p += 256) {
            const int r = p >> 6, d = p & 63;
            const float v1 = Cs[r * 132 + d];
            const float v2 = Cs[r * 132 + d + 64];
            const int s_ = m0 + r;
            const float invf = expf(-0.14391156831212788f * (float)d);
            const float ang = (float)s_ * invf;
            float sn, cs;
            sincosf(ang, &sn, &cs);
            const size_t base = ((size_t)h * S + s_) * HD;
            G[base + d]      = __float2half_rn(v1 * cs - v2 * sn);
            G[base + d + 64] = __float2half_rn(v2 * cs + v1 * sn);
        }
    } else if (mode == 2) {
        // V transpose + fused per-block column sums (fp32, from Cs)
        const int d = tid >> 1, seg = tid & 1;   // seg = which key-block half
        const size_t base = ((size_t)h * HD + d) * S + m0 + seg * 64;
        float bsum = 0.f;
#pragma unroll
        for (int rr = 0; rr < 16; rr++) {
            const float v0 = Cs[(seg * 64 + rr * 4 + 0) * 132 + d];
            const float v1 = Cs[(seg * 64 + rr * 4 + 1) * 132 + d];
            const float v2 = Cs[(seg * 64 + rr * 4 + 2) * 132 + d];
            const float v3 = Cs[(seg * 64 + rr * 4 + 3) * 132 + d];
            bsum += v0 + v1 + v2 + v3;
            ushort4 hv;
            hv.x = __half_as_ushort(__float2half_rn(v0));
            hv.y = __half_as_ushort(__float2half_rn(v1));
            hv.z = __half_as_ushort(__float2half_rn(v2));
            hv.w = __half_as_ushort(__float2half_rn(v3));
            *(ushort4*)&g_Vth[base + rr * 4] = hv;
        }
        const int kb = blockIdx.y * 2 + seg;
        g_Vblk[((size_t)h * NKB + kb) * HD + d] = bsum;
    } else {
        for (int p = tid; p < 128 * 32; p += 256) {
            const int r = p >> 5, c4 = p & 31;
            float4 v = *(float4*)&Cs[r * 132 + c4 * 4];
            *(float4*)&Cext[(size_t)(m0 + r) * HID + n0 + c4 * 4] = v;
        }
    }
}

// ---------------- vtot ----------------
__global__ void vtot_kernel() {
    const int h = blockIdx.x, d = threadIdx.x;
    float s = 0.f;
    for (int kb = 0; kb < NKB; kb++) s += g_Vblk[((size_t)h * NKB + kb) * HD + d];
    g_Vtot[h * HD + d] = s;
}

// ---------------- mma.sync block-sparse attention (fp16 1-chain, K/V double buffered) ----------------
#define QSTR 272
#define VSTR 144
#define AQ   0
#define KVST 35840
#define AK(b) (17408 + (b) * KVST)
#define AV(b) (AK(b) + 17408)
#define ASM_SMALL (17408 + 2 * KVST)   // 89088
#define SMEM_ATTN (ASM_SMALL + 64 * 4 + 128 * 4 + 32 * 4)

__global__ __launch_bounds__(128) void attn_mma() {
    extern __shared__ char smb[];
    const uint32_t sb = smem_u32(smb);
    float* lsum  = (float*)(smb + ASM_SMALL);
    float* vcorr = lsum + 64;
    int*   slist = (int*)(vcorr + 128);

    const int qb = blockIdx.x, h = blockIdx.y;
    const int tid = threadIdx.x, wm = tid >> 5, lane = tid & 31;
    const int lrow = lane & 15, lcb = (lane >> 4) << 4;

    const int cnt = g_cnt[h * NQB + qb];
    if (tid < 32) slist[tid] = g_list[(h * NQB + qb) * NKB + tid];

    {
        const size_t gq = ((size_t)h * S + qb * 64) * HD;
#pragma unroll
        for (int u = 0; u < 8; u++) {
            const int idx = tid + 128 * u;
            const int r = idx >> 4, c = idx & 15;
            CP_ASYNC16(sb + AQ + r * QSTR + c * 16, (const char*)&g_Qh[gq + (size_t)r * HD + c * 8]);
        }
        CP_COMMIT();
    }
    __syncthreads();

#define ISSUE_KV(ii, buf) do {                                                      \
    const int kb_ = slist[ii];                                                      \
    const size_t gk_ = ((size_t)h * S + kb_ * 64) * HD;                             \
    const size_t gv_ = (size_t)h * HD * S + (size_t)kb_ * 64;                       \
    _Pragma("unroll")                                                               \
    for (int u = 0; u < 8; u++) {                                                   \
        const int idx = tid + 128 * u;                                              \
        const int r = idx >> 4, c = idx & 15;                                       \
        CP_ASYNC16(sb + AK(buf) + r * QSTR + c * 16, (const char*)&g_Kh[gk_ + (size_t)r * HD + c * 8]); \
        const int rv = idx >> 3, cv = idx & 7;                                      \
        CP_ASYNC16(sb + AV(buf) + rv * VSTR + cv * 16, (const char*)&g_Vth[gv_ + (size_t)rv * S + cv * 8]); \
    }                                                                               \
    CP_COMMIT();                                                                    \
} while (0)

    if (cnt > 0) ISSUE_KV(0, 0);

    {
        float vc = g_Vtot[h * HD + tid];
        for (int ii = 0; ii < cnt; ii++)
            vc -= g_Vblk[((size_t)h * NKB + slist[ii]) * HD + tid];
        vcorr[tid] = vc * EXPC;
        if (tid < 64) lsum[tid] = (float)(S - 64 * cnt) * EXPC;
    }
    __syncthreads();

    float oacc[16][4];
#pragma unroll
    for (int i = 0; i < 16; i++)
#pragma unroll
        for (int e = 0; e < 4; e++) oacc[i][e] = 0.f;

    for (int ii = 0; ii < cnt; ii++) {
        const int buf = ii & 1;
        if (ii + 1 < cnt) {
            ISSUE_KV(ii + 1, buf ^ 1);
            asm volatile("cp.async.wait_group 1;" ::: "memory");
        } else {
            asm volatile("cp.async.wait_group 0;" ::: "memory");
        }
        __syncthreads();

        float sacc[8][4];
#pragma unroll
        for (int i = 0; i < 8; i++)
#pragma unroll
            for (int e = 0; e < 4; e++) sacc[i][e] = 0.f;
#pragma unroll
        for (int kt = 0; kt < 8; kt++) {
            uint32_t qh[4];
            ldsm4(qh, sb + AQ + (wm * 16 + lrow) * QSTR + kt * 32 + lcb);
#pragma unroll
            for (int jt = 0; jt < 4; jt++) {
                uint32_t kh[4];
                ldsm4(kh, sb + AK(buf) + (jt * 16 + lrow) * QSTR + kt * 32 + lcb);
                mma_f16(sacc[2 * jt],     qh, kh[0], kh[2]);
                mma_f16(sacc[2 * jt + 1], qh, kh[1], kh[3]);
            }
        }

        uint32_t pah[4][4];
        float rs0 = 0.f, rs1 = 0.f;
#pragma unroll
        for (int nt = 0; nt < 8; nt++) {
            const float p0 = __expf(fmaf(sacc[nt][0], SCALE, -ESHIFT));
            const float p1 = __expf(fmaf(sacc[nt][1], SCALE, -ESHIFT));
            const float p2 = __expf(fmaf(sacc[nt][2], SCALE, -ESHIFT));
            const float p3 = __expf(fmaf(sacc[nt][3], SCALE, -ESHIFT));
            rs0 += p0 + p1;
            rs1 += p2 + p3;
            const int g = nt >> 1, o = (nt & 1) * 2;
            pah[g][o]     = packh2(p0, p1);
            pah[g][o + 1] = packh2(p2, p3);
        }
        rs0 += __shfl_xor_sync(0xffffffffu, rs0, 1);
        rs0 += __shfl_xor_sync(0xffffffffu, rs0, 2);
        rs1 += __shfl_xor_sync(0xffffffffu, rs1, 1);
        rs1 += __shfl_xor_sync(0xffffffffu, rs1, 2);
        if ((lane & 3) == 0) {
            lsum[wm * 16 + (lane >> 2)]     += rs0;
            lsum[wm * 16 + (lane >> 2) + 8] += rs1;
        }

#pragma unroll
        for (int g = 0; g < 4; g++) {
#pragma unroll
            for (int dt = 0; dt < 8; dt++) {
                uint32_t vh[4];
                ldsm4(vh, sb + AV(buf) + (dt * 16 + lrow) * VSTR + g * 32 + lcb);
                mma_f16(oacc[2 * dt],     pah[g], vh[0], vh[2]);
                mma_f16(oacc[2 * dt + 1], pah[g], vh[1], vh[3]);
            }
        }
        __syncthreads();
    }
    asm volatile("cp.async.wait_group 0;" ::: "memory");
    __syncthreads();

    const int r0 = wm * 16 + (lane >> 2);
    const float il0 = 1.f / lsum[r0];
    const float il1 = 1.f / lsum[r0 + 8];
    const int cbase = 2 * (lane & 3);
    const size_t ob0 = (size_t)(qb * 64 + r0) * HID + h * HD;
    const size_t ob1 = ob0 + (size_t)8 * HID;
#pragma unroll
    for (int ot = 0; ot < 16; ot++) {
        const int c = 8 * ot + cbase;
        const float a0 = (oacc[ot][0] + vcorr[c]) * il0;
        const float a1 = (oacc[ot][1] + vcorr[c + 1]) * il0;
        const float b0 = (oacc[ot][2] + vcorr[c]) * il1;
        const float b1 = (oacc[ot][3] + vcorr[c + 1]) * il1;
        ((uint32_t*)g_ATh)[(ob0 + c) >> 1] = packh2(a0, a1);
        ((uint32_t*)g_ATh)[(ob1 + c) >> 1] = packh2(b0, b1);
    }
}

// ---------------------------------------------------------------------------
extern "C" void kernel_launch(void* const* d_in, const int* in_sizes, int n_in,
                              void* d_out, int out_size) {
    const float* X  = (const float*)d_in[0];
    const float* qw = (const float*)d_in[1];
    const float* kw = (const float*)d_in[2];
    const float* vw = (const float*)d_in[3];
    const float* ow = (const float*)d_in[4];
    const float* sp = (const float*)d_in[5];
    float* out = (float*)d_out;

    cudaFuncSetAttribute(mma_gemm, cudaFuncAttributeMaxDynamicSharedMemorySize, GEMM_SMEM);
    cudaFuncSetAttribute(attn_mma, cudaFuncAttributeMaxDynamicSharedMemorySize, SMEM_ATTN);

    convert_h<<<(S * HID / 4 + 255) / 256, 256>>>(X);            // 0
    convert_T4<<<dim3(64, 64, 4), dim3(32, 8)>>>(qw, kw, vw, ow);// 1
    mask_kernel<<<dim3(NH, 4), 256>>>(sp);                       // 2
    mma_gemm<<<dim3(16, 16, 3), 256, GEMM_SMEM>>>(nullptr, -1);  // 3 <- ncu window
    list_kernel<<<1, 512>>>();                                   // 4
    vtot_kernel<<<NH, HD>>>();                                   // 5
    attn_mma<<<dim3(NQB, NH), 128, SMEM_ATTN>>>();               // 6
    mma_gemm<<<dim3(16, 16), 256, GEMM_SMEM>>>(out, 3);          // 7
}

// round 15
// speedup vs baseline: 2.4523x; 1.0933x over previous
#include <cuda_runtime.h>
#include <cuda_fp16.h>
#include <math.h>
#include <stdint.h>

// Problem constants
#define S     2048
#define HID   2048
#define NH    16
#define HD    128
#define BS_   64
#define NQB   32
#define NKB   32
#define KSEL  511
#define SCALE 0.08838834764831845f
#define ESHIFT 4.0f
#define EXPC  0.01831563889f   // e^-4

// ---------------- device scratch (allocation-free) ----------------
__device__ float g_Vblk[NH * NKB * HD];
__device__ int   g_mask[NH * NQB * NKB];
__device__ int   g_list[NH * NQB * NKB];
__device__ int   g_cnt[NH * NQB];

// plain fp16 operands everywhere
__device__ __half g_Xh[S * HID];
__device__ __half g_Wh[4][HID * HID];
__device__ __half g_ATh[S * HID];

__device__ __half g_Qh[NH * S * HD];
__device__ __half g_Kh[NH * S * HD];
__device__ __half g_Vth[NH * HD * S];    // [h][d][s]

// ---------------- helpers ----------------
__device__ __forceinline__ uint32_t smem_u32(const void* p) {
    uint32_t a;
    asm("{ .reg .u64 t; cvta.to.shared.u64 t, %1; cvt.u32.u64 %0, t; }" : "=r"(a) : "l"(p));
    return a;
}
__device__ __forceinline__ void ldsm4(uint32_t (&r)[4], uint32_t addr) {
    asm volatile("ldmatrix.sync.aligned.m8n8.x4.shared.b16 {%0,%1,%2,%3}, [%4];"
        : "=r"(r[0]), "=r"(r[1]), "=r"(r[2]), "=r"(r[3]) : "r"(addr));
}
__device__ __forceinline__ void mma_f16(float (&d)[4], const uint32_t (&a)[4],
                                        uint32_t b0, uint32_t b1) {
    asm volatile("mma.sync.aligned.m16n8k16.row.col.f32.f16.f16.f32 "
        "{%0,%1,%2,%3}, {%4,%5,%6,%7}, {%8,%9}, {%0,%1,%2,%3};"
        : "+f"(d[0]), "+f"(d[1]), "+f"(d[2]), "+f"(d[3])
        : "r"(a[0]), "r"(a[1]), "r"(a[2]), "r"(a[3]), "r"(b0), "r"(b1));
}
#define CP_ASYNC16(dst, src) \
    asm volatile("cp.async.cg.shared.global [%0], [%1], 16;" :: "r"(dst), "l"(src))
#define CP_COMMIT() asm volatile("cp.async.commit_group;" ::: "memory")

__device__ __forceinline__ uint32_t packh2(float a, float b) {
    __half2 h = __floats2half2_rn(a, b);
    return *reinterpret_cast<uint32_t*>(&h);
}

// ---------------- conversions ----------------
__global__ void convert_h(const float* __restrict__ src) {
    int i = blockIdx.x * blockDim.x + threadIdx.x;
    float4 v = ((const float4*)src)[i];
    ushort4 hv = { __half_as_ushort(__float2half_rn(v.x)),
                   __half_as_ushort(__float2half_rn(v.y)),
                   __half_as_ushort(__float2half_rn(v.z)),
                   __half_as_ushort(__float2half_rn(v.w)) };
    ((ushort4*)g_Xh)[i] = hv;
}

__global__ void convert_T4(const float* __restrict__ qw, const float* __restrict__ kw,
                           const float* __restrict__ vw, const float* __restrict__ ow) {
    __shared__ float t[32][33];
    const int widx = blockIdx.z;
    const float* W = (widx == 0) ? qw : (widx == 1) ? kw : (widx == 2) ? vw : ow;
    const int k0 = blockIdx.y * 32, n0 = blockIdx.x * 32;
    const int tx = threadIdx.x, ty = threadIdx.y;
#pragma unroll
    for (int j = 0; j < 4; j++)
        t[ty + 8 * j][tx] = W[(size_t)(k0 + ty + 8 * j) * HID + n0 + tx];
    __syncthreads();
#pragma unroll
    for (int j = 0; j < 4; j++) {
        const int n = n0 + ty + 8 * j, k = k0 + tx;
        g_Wh[widx][(size_t)n * HID + k] = __float2half_rn(t[tx][ty + 8 * j]);
    }
}

// ---------------- mask (parallel count) + fused list build ----------------
__global__ void mask_kernel(const float* __restrict__ sp) {
    __shared__ float v[1024];
    __shared__ int msk[256];
    const int h = blockIdx.x, chunk = blockIdx.y, t = threadIdx.x;  // 256 thr
    for (int i = t; i < 1024; i += 256) v[i] = sp[h * 1024 + i];
    __syncthreads();
    const int idx = chunk * 256 + t;
    const float mine = v[idx];
    int c = 0;
#pragma unroll 8
    for (int i = 0; i < 1024; i++) c += (v[i] >= mine);
    const int sel = (c <= KSEL) ? 1 : 0;
    g_mask[h * 1024 + idx] = sel;
    msk[t] = sel;
    __syncthreads();
    if (t < 8) {   // 8 qb rows per chunk
        const int qb = chunk * 8 + t;
        int cc = 0;
        for (int kb = 0; kb < NKB; kb++)
            if (msk[t * 32 + kb]) g_list[(h * NQB + qb) * NKB + cc++] = kb;
        g_cnt[h * NQB + qb] = cc;
    }
}

// ---------------- mma.sync fp16 single-chain GEMM, 4-stage / 1 sync per chunk ----------------
#define SROW    80
#define TILE_SM (128 * SROW)        // 10240
#define STAGE   (2 * TILE_SM)       // 20480 (A + B)
#define GEMM_SMEM (4 * STAGE)       // 81920 >= epilogue 67584

__global__ __launch_bounds__(256) void mma_gemm(float* __restrict__ Cext, int modeArg) {
    extern __shared__ char sm8[];
    const uint32_t sb = smem_u32(sm8);
    const int tid = threadIdx.x, wid = tid >> 5, lane = tid & 31;
    const int m0 = blockIdx.y * 128, n0 = blockIdx.x * 128;
    const int wm = wid & 1, wn = wid >> 1;
    const int mode = (modeArg < 0) ? (int)blockIdx.z : modeArg;

    const __half* Ah = (mode == 3) ? g_ATh : g_Xh;
    const __half* Bh = g_Wh[mode];

    float acc[4][4][4];
#pragma unroll
    for (int mt = 0; mt < 4; mt++)
#pragma unroll
        for (int nt = 0; nt < 4; nt++)
#pragma unroll
            for (int e = 0; e < 4; e++) acc[mt][nt][e] = 0.f;

#define ISSUE(cc, buf) do {                                                        \
    const int k0_ = (cc) * 32;                                                     \
    const uint32_t s0_ = sb + (buf) * STAGE;                                       \
    _Pragma("unroll")                                                              \
    for (int u = 0; u < 2; u++) {                                                  \
        const int idx = tid + 256 * u;                                             \
        const int r = idx >> 2, c16 = idx & 3;                                     \
        const uint32_t doff = r * SROW + c16 * 16;                                 \
        CP_ASYNC16(s0_ + doff,           (const char*)&Ah[(size_t)(m0 + r) * HID + k0_ + c16 * 8]); \
        CP_ASYNC16(s0_ + TILE_SM + doff, (const char*)&Bh[(size_t)(n0 + r) * HID + k0_ + c16 * 8]); \
    }                                                                              \
    CP_COMMIT();                                                                   \
} while (0)

    // 4 buffers, prefetch depth 2: buffer c%4 is overwritten by ISSUE(c+4) at
    // iteration c+2, i.e. after the sync of iteration c+1 (all threads past
    // compute(c)). -> single __syncthreads per chunk.
    ISSUE(0, 0);
    ISSUE(1, 1);
    for (int c = 0; c < 64; c++) {
        if (c < 62) {
            ISSUE(c + 2, (c + 2) & 3);
            asm volatile("cp.async.wait_group 2;" ::: "memory");
        } else if (c == 62) {
            asm volatile("cp.async.wait_group 1;" ::: "memory");
        } else {
            asm volatile("cp.async.wait_group 0;" ::: "memory");
        }
        __syncthreads();

        const uint32_t s0 = sb + (c & 3) * STAGE;
        const int kb2 = ((lane >> 4) * 8) * 2;
        const int ar = wm * 64 + (lane & 15);
        const int br = wn * 32 + (lane & 15);
#pragma unroll
        for (int ks = 0; ks < 2; ks++) {
            const int kbyte = ks * 32 + kb2;
            uint32_t ah[4][4];
#pragma unroll
            for (int mt = 0; mt < 4; mt++)
                ldsm4(ah[mt], s0 + (ar + mt * 16) * SROW + kbyte);
            uint32_t bh[2][4];
#pragma unroll
            for (int bt = 0; bt < 2; bt++)
                ldsm4(bh[bt], s0 + TILE_SM + (br + bt * 16) * SROW + kbyte);
#pragma unroll
            for (int mt = 0; mt < 4; mt++)
#pragma unroll
                for (int nt = 0; nt < 4; nt++) {
                    const int bt = nt >> 1, sel = nt & 1;
                    mma_f16(acc[mt][nt], ah[mt], bh[bt][sel], bh[bt][sel + 2]);
                }
        }
    }
    __syncthreads();   // all reads done before Cs overwrites stage buffers

    // ---- epilogue via smem tile ----
    float* Cs = (float*)sm8;   // 128 x 132
#pragma unroll
    for (int mt = 0; mt < 4; mt++)
#pragma unroll
        for (int nt = 0; nt < 4; nt++) {
            const int r = wm * 64 + mt * 16 + (lane >> 2);
            const int col = wn * 32 + nt * 8 + (lane & 3) * 2;
            Cs[r * 132 + col]           = acc[mt][nt][0];
            Cs[r * 132 + col + 1]       = acc[mt][nt][1];
            Cs[(r + 8) * 132 + col]     = acc[mt][nt][2];
            Cs[(r + 8) * 132 + col + 1] = acc[mt][nt][3];
        }
    __syncthreads();

    const int h = blockIdx.x;
    if (mode <= 1) {
        __half* G = mode ? g_Kh : g_Qh;
        for (int p = tid; p < 128 * 64; p += 256) {
            const int r = p >> 6, d = p & 63;
            const float v1 = Cs[r * 132 + d];
            const float v2 = Cs[r * 132 + d + 64];
            const int s_ = m0 + r;
            const float invf = expf(-0.14391156831212788f * (float)d);
            const float ang = (float)s_ * invf;
            float sn, cs;
            sincosf(ang, &sn, &cs);
            const size_t base = ((size_t)h * S + s_) * HD;
            G[base + d]      = __float2half_rn(v1 * cs - v2 * sn);
            G[base + d + 64] = __float2half_rn(v2 * cs + v1 * sn);
        }
    } else if (mode == 2) {
        // V transpose + fused per-block column sums (fp32, from Cs)
        const int d = tid >> 1, seg = tid & 1;
        const size_t base = ((size_t)h * HD + d) * S + m0 + seg * 64;
        float bsum = 0.f;
#pragma unroll
        for (int rr = 0; rr < 16; rr++) {
            const float v0 = Cs[(seg * 64 + rr * 4 + 0) * 132 + d];
            const float v1 = Cs[(seg * 64 + rr * 4 + 1) * 132 + d];
            const float v2 = Cs[(seg * 64 + rr * 4 + 2) * 132 + d];
            const float v3 = Cs[(seg * 64 + rr * 4 + 3) * 132 + d];
            bsum += v0 + v1 + v2 + v3;
            ushort4 hv;
            hv.x = __half_as_ushort(__float2half_rn(v0));
            hv.y = __half_as_ushort(__float2half_rn(v1));
            hv.z = __half_as_ushort(__float2half_rn(v2));
            hv.w = __half_as_ushort(__float2half_rn(v3));
            *(ushort4*)&g_Vth[base + rr * 4] = hv;
        }
        const int kb = blockIdx.y * 2 + seg;
        g_Vblk[((size_t)h * NKB + kb) * HD + d] = bsum;
    } else {
        for (int p = tid; p < 128 * 32; p += 256) {
            const int r = p >> 5, c4 = p & 31;
            float4 v = *(float4*)&Cs[r * 132 + c4 * 4];
            *(float4*)&Cext[(size_t)(m0 + r) * HID + n0 + c4 * 4] = v;
        }
    }
}

// ---------------- mma.sync block-sparse attention (fp16 1-chain, K/V double buffered) ----------------
#define QSTR 272
#define VSTR 144
#define AQ   0
#define KVST 35840
#define AK(b) (17408 + (b) * KVST)
#define AV(b) (AK(b) + 17408)
#define ASM_SMALL (17408 + 2 * KVST)   // 89088
#define SMEM_ATTN (ASM_SMALL + 64 * 4 + 128 * 4 + 32 * 4)

__global__ __launch_bounds__(128) void attn_mma() {
    extern __shared__ char smb[];
    const uint32_t sb = smem_u32(smb);
    float* lsum  = (float*)(smb + ASM_SMALL);
    float* vcorr = lsum + 64;
    int*   slist = (int*)(vcorr + 128);

    const int qb = blockIdx.x, h = blockIdx.y;
    const int tid = threadIdx.x, wm = tid >> 5, lane = tid & 31;
    const int lrow = lane & 15, lcb = (lane >> 4) << 4;

    const int cnt = g_cnt[h * NQB + qb];
    if (tid < 32) slist[tid] = g_list[(h * NQB + qb) * NKB + tid];

    {
        const size_t gq = ((size_t)h * S + qb * 64) * HD;
#pragma unroll
        for (int u = 0; u < 8; u++) {
            const int idx = tid + 128 * u;
            const int r = idx >> 4, c = idx & 15;
            CP_ASYNC16(sb + AQ + r * QSTR + c * 16, (const char*)&g_Qh[gq + (size_t)r * HD + c * 8]);
        }
        CP_COMMIT();
    }
    __syncthreads();

#define ISSUE_KV(ii, buf) do {                                                      \
    const int kb_ = slist[ii];                                                      \
    const size_t gk_ = ((size_t)h * S + kb_ * 64) * HD;                             \
    const size_t gv_ = (size_t)h * HD * S + (size_t)kb_ * 64;                       \
    _Pragma("unroll")                                                               \
    for (int u = 0; u < 8; u++) {                                                   \
        const int idx = tid + 128 * u;                                              \
        const int r = idx >> 4, c = idx & 15;                                       \
        CP_ASYNC16(sb + AK(buf) + r * QSTR + c * 16, (const char*)&g_Kh[gk_ + (size_t)r * HD + c * 8]); \
        const int rv = idx >> 3, cv = idx & 7;                                      \
        CP_ASYNC16(sb + AV(buf) + rv * VSTR + cv * 16, (const char*)&g_Vth[gv_ + (size_t)rv * S + cv * 8]); \
    }                                                                               \
    CP_COMMIT();                                                                    \
} while (0)

    if (cnt > 0) ISSUE_KV(0, 0);

    // zero-block V correction = complement sum over unselected blocks
    {
        const int* mrow = &g_mask[(h * NQB + qb) * NKB];
        float vc = 0.f;
        for (int kb = 0; kb < NKB; kb++)
            if (!mrow[kb]) vc += g_Vblk[((size_t)h * NKB + kb) * HD + tid];
        vcorr[tid] = vc * EXPC;
        if (tid < 64) lsum[tid] = (float)(S - 64 * cnt) * EXPC;
    }
    __syncthreads();

    float oacc[16][4];
#pragma unroll
    for (int i = 0; i < 16; i++)
#pragma unroll
        for (int e = 0; e < 4; e++) oacc[i][e] = 0.f;

    for (int ii = 0; ii < cnt; ii++) {
        const int buf = ii & 1;
        if (ii + 1 < cnt) {
            ISSUE_KV(ii + 1, buf ^ 1);
            asm volatile("cp.async.wait_group 1;" ::: "memory");
        } else {
            asm volatile("cp.async.wait_group 0;" ::: "memory");
        }
        __syncthreads();

        float sacc[8][4];
#pragma unroll
        for (int i = 0; i < 8; i++)
#pragma unroll
            for (int e = 0; e < 4; e++) sacc[i][e] = 0.f;
#pragma unroll
        for (int kt = 0; kt < 8; kt++) {
            uint32_t qh[4];
            ldsm4(qh, sb + AQ + (wm * 16 + lrow) * QSTR + kt * 32 + lcb);
#pragma unroll
            for (int jt = 0; jt < 4; jt++) {
                uint32_t kh[4];
                ldsm4(kh, sb + AK(buf) + (jt * 16 + lrow) * QSTR + kt * 32 + lcb);
                mma_f16(sacc[2 * jt],     qh, kh[0], kh[2]);
                mma_f16(sacc[2 * jt + 1], qh, kh[1], kh[3]);
            }
        }

        uint32_t pah[4][4];
        float rs0 = 0.f, rs1 = 0.f;
#pragma unroll
        for (int nt = 0; nt < 8; nt++) {
            const float p0 = __expf(fmaf(sacc[nt][0], SCALE, -ESHIFT));
            const float p1 = __expf(fmaf(sacc[nt][1], SCALE, -ESHIFT));
            const float p2 = __expf(fmaf(sacc[nt][2], SCALE, -ESHIFT));
            const float p3 = __expf(fmaf(sacc[nt][3], SCALE, -ESHIFT));
            rs0 += p0 + p1;
            rs1 += p2 + p3;
            const int g = nt >> 1, o = (nt & 1) * 2;
            pah[g][o]     = packh2(p0, p1);
            pah[g][o + 1] = packh2(p2, p3);
        }
        rs0 += __shfl_xor_sync(0xffffffffu, rs0, 1);
        rs0 += __shfl_xor_sync(0xffffffffu, rs0, 2);
        rs1 += __shfl_xor_sync(0xffffffffu, rs1, 1);
        rs1 += __shfl_xor_sync(0xffffffffu, rs1, 2);
        if ((lane & 3) == 0) {
            lsum[wm * 16 + (lane >> 2)]     += rs0;
            lsum[wm * 16 + (lane >> 2) + 8] += rs1;
        }

#pragma unroll
        for (int g = 0; g < 4; g++) {
#pragma unroll
            for (int dt = 0; dt < 8; dt++) {
                uint32_t vh[4];
                ldsm4(vh, sb + AV(buf) + (dt * 16 + lrow) * VSTR + g * 32 + lcb);
                mma_f16(oacc[2 * dt],     pah[g], vh[0], vh[2]);
                mma_f16(oacc[2 * dt + 1], pah[g], vh[1], vh[3]);
            }
        }
        __syncthreads();
    }
    asm volatile("cp.async.wait_group 0;" ::: "memory");
    __syncthreads();

    const int r0 = wm * 16 + (lane >> 2);
    const float il0 = 1.f / lsum[r0];
    const float il1 = 1.f / lsum[r0 + 8];
    const int cbase = 2 * (lane & 3);
    const size_t ob0 = (size_t)(qb * 64 + r0) * HID + h * HD;
    const size_t ob1 = ob0 + (size_t)8 * HID;
#pragma unroll
    for (int ot = 0; ot < 16; ot++) {
        const int c = 8 * ot + cbase;
        const float a0 = (oacc[ot][0] + vcorr[c]) * il0;
        const float a1 = (oacc[ot][1] + vcorr[c + 1]) * il0;
        const float b0 = (oacc[ot][2] + vcorr[c]) * il1;
        const float b1 = (oacc[ot][3] + vcorr[c + 1]) * il1;
        ((uint32_t*)g_ATh)[(ob0 + c) >> 1] = packh2(a0, a1);
        ((uint32_t*)g_ATh)[(ob1 + c) >> 1] = packh2(b0, b1);
    }
}

// ---------------------------------------------------------------------------
extern "C" void kernel_launch(void* const* d_in, const int* in_sizes, int n_in,
                              void* d_out, int out_size) {
    const float* X  = (const float*)d_in[0];
    const float* qw = (const float*)d_in[1];
    const float* kw = (const float*)d_in[2];
    const float* vw = (const float*)d_in[3];
    const float* ow = (const float*)d_in[4];
    const float* sp = (const float*)d_in[5];
    float* out = (float*)d_out;

    cudaFuncSetAttribute(mma_gemm, cudaFuncAttributeMaxDynamicSharedMemorySize, GEMM_SMEM);
    cudaFuncSetAttribute(attn_mma, cudaFuncAttributeMaxDynamicSharedMemorySize, SMEM_ATTN);

    convert_h<<<(S * HID / 4 + 255) / 256, 256>>>(X);            // 0
    convert_T4<<<dim3(64, 64, 4), dim3(32, 8)>>>(qw, kw, vw, ow);// 1
    mask_kernel<<<dim3(NH, 4), 256>>>(sp);                       // 2
    mma_gemm<<<dim3(16, 16, 3), 256, GEMM_SMEM>>>(nullptr, -1);  // 3 <- ncu window
    attn_mma<<<dim3(NQB, NH), 128, SMEM_ATTN>>>();               // 4
    mma_gemm<<<dim3(16, 16), 256, GEMM_SMEM>>>(out, 3);          // 5
}

// round 16
// speedup vs baseline: 2.6107x; 1.0646x over previous
#include <cuda_runtime.h>
#include <cuda_fp16.h>
#include <math.h>
#include <stdint.h>

// Problem constants
#define S     2048
#define HID   2048
#define NH    16
#define HD    128
#define BS_   64
#define NQB   32
#define NKB   32
#define KSEL  511
#define SCALE 0.08838834764831845f
#define ESHIFT 4.0f
#define EXPC  0.01831563889f   // e^-4

// ---------------- device scratch (allocation-free) ----------------
__device__ float g_Vblk[NH * NKB * HD];
__device__ int   g_mask[NH * NQB * NKB];
__device__ int   g_list[NH * NQB * NKB];
__device__ int   g_cnt[NH * NQB];

// plain fp16 operands everywhere
__device__ __half g_Xh[S * HID];
__device__ __half g_Wh[4][HID * HID];
__device__ __half g_ATh[S * HID];

__device__ __half g_Qh[NH * S * HD];
__device__ __half g_Kh[NH * S * HD];
__device__ __half g_Vth[NH * HD * S];    // [h][d][s]

// ---------------- helpers ----------------
__device__ __forceinline__ uint32_t smem_u32(const void* p) {
    uint32_t a;
    asm("{ .reg .u64 t; cvta.to.shared.u64 t, %1; cvt.u32.u64 %0, t; }" : "=r"(a) : "l"(p));
    return a;
}
__device__ __forceinline__ void ldsm4(uint32_t (&r)[4], uint32_t addr) {
    asm volatile("ldmatrix.sync.aligned.m8n8.x4.shared.b16 {%0,%1,%2,%3}, [%4];"
        : "=r"(r[0]), "=r"(r[1]), "=r"(r[2]), "=r"(r[3]) : "r"(addr));
}
__device__ __forceinline__ void mma_f16(float (&d)[4], const uint32_t (&a)[4],
                                        uint32_t b0, uint32_t b1) {
    asm volatile("mma.sync.aligned.m16n8k16.row.col.f32.f16.f16.f32 "
        "{%0,%1,%2,%3}, {%4,%5,%6,%7}, {%8,%9}, {%0,%1,%2,%3};"
        : "+f"(d[0]), "+f"(d[1]), "+f"(d[2]), "+f"(d[3])
        : "r"(a[0]), "r"(a[1]), "r"(a[2]), "r"(a[3]), "r"(b0), "r"(b1));
}
#define CP_ASYNC16(dst, src) \
    asm volatile("cp.async.cg.shared.global [%0], [%1], 16;" :: "r"(dst), "l"(src))
#define CP_COMMIT() asm volatile("cp.async.commit_group;" ::: "memory")

__device__ __forceinline__ uint32_t packh2(float a, float b) {
    __half2 h = __floats2half2_rn(a, b);
    return *reinterpret_cast<uint32_t*>(&h);
}

// ---------------- conversions ----------------
__global__ void convert_h(const float* __restrict__ src) {
    int i = blockIdx.x * blockDim.x + threadIdx.x;
    float4 v = ((const float4*)src)[i];
    ushort4 hv = { __half_as_ushort(__float2half_rn(v.x)),
                   __half_as_ushort(__float2half_rn(v.y)),
                   __half_as_ushort(__float2half_rn(v.z)),
                   __half_as_ushort(__float2half_rn(v.w)) };
    ((ushort4*)g_Xh)[i] = hv;
}

__global__ void convert_T4(const float* __restrict__ qw, const float* __restrict__ kw,
                           const float* __restrict__ vw, const float* __restrict__ ow) {
    __shared__ float t[32][33];
    const int widx = blockIdx.z;
    const float* W = (widx == 0) ? qw : (widx == 1) ? kw : (widx == 2) ? vw : ow;
    const int k0 = blockIdx.y * 32, n0 = blockIdx.x * 32;
    const int tx = threadIdx.x, ty = threadIdx.y;
#pragma unroll
    for (int j = 0; j < 4; j++)
        t[ty + 8 * j][tx] = W[(size_t)(k0 + ty + 8 * j) * HID + n0 + tx];
    __syncthreads();
#pragma unroll
    for (int j = 0; j < 4; j++) {
        const int n = n0 + ty + 8 * j, k = k0 + tx;
        g_Wh[widx][(size_t)n * HID + k] = __float2half_rn(t[tx][ty + 8 * j]);
    }
}

// ---------------- mask (parallel count) + fused list build ----------------
__global__ void mask_kernel(const float* __restrict__ sp) {
    __shared__ float v[1024];
    __shared__ int msk[256];
    const int h = blockIdx.x, chunk = blockIdx.y, t = threadIdx.x;  // 256 thr
    for (int i = t; i < 1024; i += 256) v[i] = sp[h * 1024 + i];
    __syncthreads();
    const int idx = chunk * 256 + t;
    const float mine = v[idx];
    int c = 0;
#pragma unroll 8
    for (int i = 0; i < 1024; i++) c += (v[i] >= mine);
    const int sel = (c <= KSEL) ? 1 : 0;
    g_mask[h * 1024 + idx] = sel;
    msk[t] = sel;
    __syncthreads();
    if (t < 8) {
        const int qb = chunk * 8 + t;
        int cc = 0;
        for (int kb = 0; kb < NKB; kb++)
            if (msk[t * 32 + kb]) g_list[(h * NQB + qb) * NKB + cc++] = kb;
        g_cnt[h * NQB + qb] = cc;
    }
}

// ---------------- mma.sync fp16 GEMM: 128 thr, 4 warps @ 64x64, 4-stage ----------------
#define SROW    80
#define TILE_SM (128 * SROW)        // 10240
#define STAGE   (2 * TILE_SM)       // 20480 (A + B)
#define GEMM_SMEM 81920             // 4 stages; >= epilogue 67584

__global__ __launch_bounds__(128) void mma_gemm(float* __restrict__ Cext, int modeArg) {
    extern __shared__ char sm8[];
    const uint32_t sb = smem_u32(sm8);
    const int tid = threadIdx.x, wid = tid >> 5, lane = tid & 31;
    const int m0 = blockIdx.y * 128, n0 = blockIdx.x * 128;
    const int wm = wid & 1, wn = wid >> 1;        // 2 x 2 warp grid, 64x64 each
    const int mode = (modeArg < 0) ? (int)blockIdx.z : modeArg;

    const __half* Ah = (mode == 3) ? g_ATh : g_Xh;
    const __half* Bh = g_Wh[mode];

    float acc[4][8][4];
#pragma unroll
    for (int mt = 0; mt < 4; mt++)
#pragma unroll
        for (int nt = 0; nt < 8; nt++)
#pragma unroll
            for (int e = 0; e < 4; e++) acc[mt][nt][e] = 0.f;

#define ISSUE(cc, buf) do {                                                        \
    const int k0_ = (cc) * 32;                                                     \
    const uint32_t s0_ = sb + (buf) * STAGE;                                       \
    _Pragma("unroll")                                                              \
    for (int u = 0; u < 4; u++) {                                                  \
        const int idx = tid + 128 * u;                                             \
        const int r = idx >> 2, c16 = idx & 3;                                     \
        const uint32_t doff = r * SROW + c16 * 16;                                 \
        CP_ASYNC16(s0_ + doff,           (const char*)&Ah[(size_t)(m0 + r) * HID + k0_ + c16 * 8]); \
        CP_ASYNC16(s0_ + TILE_SM + doff, (const char*)&Bh[(size_t)(n0 + r) * HID + k0_ + c16 * 8]); \
    }                                                                              \
    CP_COMMIT();                                                                   \
} while (0)

    ISSUE(0, 0);
    ISSUE(1, 1);
    for (int c = 0; c < 64; c++) {
        if (c < 62) {
            ISSUE(c + 2, (c + 2) & 3);
            asm volatile("cp.async.wait_group 2;" ::: "memory");
        } else if (c == 62) {
            asm volatile("cp.async.wait_group 1;" ::: "memory");
        } else {
            asm volatile("cp.async.wait_group 0;" ::: "memory");
        }
        __syncthreads();

        const uint32_t s0 = sb + (c & 3) * STAGE;
        const int kb2 = ((lane >> 4) * 8) * 2;
        const int ar = wm * 64 + (lane & 15);
        const int br = wn * 64 + (lane & 15);
#pragma unroll
        for (int ks = 0; ks < 2; ks++) {
            const int kbyte = ks * 32 + kb2;
            uint32_t ah[4][4];
#pragma unroll
            for (int mt = 0; mt < 4; mt++)
                ldsm4(ah[mt], s0 + (ar + mt * 16) * SROW + kbyte);
            uint32_t bh[4][4];
#pragma unroll
            for (int bt = 0; bt < 4; bt++)
                ldsm4(bh[bt], s0 + TILE_SM + (br + bt * 16) * SROW + kbyte);
#pragma unroll
            for (int mt = 0; mt < 4; mt++)
#pragma unroll
                for (int nt = 0; nt < 8; nt++) {
                    const int bt = nt >> 1, sel = nt & 1;
                    mma_f16(acc[mt][nt], ah[mt], bh[bt][sel], bh[bt][sel + 2]);
                }
        }
    }
    __syncthreads();

    // ---- epilogue via smem tile ----
    float* Cs = (float*)sm8;   // 128 x 132
#pragma unroll
    for (int mt = 0; mt < 4; mt++)
#pragma unroll
        for (int nt = 0; nt < 8; nt++) {
            const int r = wm * 64 + mt * 16 + (lane >> 2);
            const int col = wn * 64 + nt * 8 + (lane & 3) * 2;
            Cs[r * 132 + col]           = acc[mt][nt][0];
            Cs[r * 132 + col + 1]       = acc[mt][nt][1];
            Cs[(r + 8) * 132 + col]     = acc[mt][nt][2];
            Cs[(r + 8) * 132 + col + 1] = acc[mt][nt][3];
        }
    __syncthreads();

    const int h = blockIdx.x;
    if (mode <= 1) {
        __half* G = mode ? g_Kh : g_Qh;
        for (int p = tid; p < 128 * 64; p += 128) {
            const int r = p >> 6, d = p & 63;
            const float v1 = Cs[r * 132 + d];
            const float v2 = Cs[r * 132 + d + 64];
            const int s_ = m0 + r;
            const float invf = expf(-0.14391156831212788f * (float)d);
            const float ang = (float)s_ * invf;
            float sn, cs;
            sincosf(ang, &sn, &cs);
            const size_t base = ((size_t)h * S + s_) * HD;
            G[base + d]      = __float2half_rn(v1 * cs - v2 * sn);
            G[base + d + 64] = __float2half_rn(v2 * cs + v1 * sn);
        }
    } else if (mode == 2) {
        // V transpose + fused per-block column sums (fp32, from Cs)
        const int d = tid;   // 0..127
#pragma unroll
        for (int seg = 0; seg < 2; seg++) {
            const size_t base = ((size_t)h * HD + d) * S + m0 + seg * 64;
            float bsum = 0.f;
#pragma unroll
            for (int rr = 0; rr < 16; rr++) {
                const float v0 = Cs[(seg * 64 + rr * 4 + 0) * 132 + d];
                const float v1 = Cs[(seg * 64 + rr * 4 + 1) * 132 + d];
                const float v2 = Cs[(seg * 64 + rr * 4 + 2) * 132 + d];
                const float v3 = Cs[(seg * 64 + rr * 4 + 3) * 132 + d];
                bsum += v0 + v1 + v2 + v3;
                ushort4 hv;
                hv.x = __half_as_ushort(__float2half_rn(v0));
                hv.y = __half_as_ushort(__float2half_rn(v1));
                hv.z = __half_as_ushort(__float2half_rn(v2));
                hv.w = __half_as_ushort(__float2half_rn(v3));
                *(ushort4*)&g_Vth[base + rr * 4] = hv;
            }
            const int kb = blockIdx.y * 2 + seg;
            g_Vblk[((size_t)h * NKB + kb) * HD + d] = bsum;
        }
    } else {
        for (int p = tid; p < 128 * 32; p += 128) {
            const int r = p >> 5, c4 = p & 31;
            float4 v = *(float4*)&Cs[r * 132 + c4 * 4];
            *(float4*)&Cext[(size_t)(m0 + r) * HID + n0 + c4 * 4] = v;
        }
    }
}

// ---------------- mma.sync block-sparse attention (fp16 1-chain, K/V double buffered) ----------------
#define QSTR 272
#define VSTR 144
#define AQ   0
#define KVST 35840
#define AK(b) (17408 + (b) * KVST)
#define AV(b) (AK(b) + 17408)
#define ASM_SMALL (17408 + 2 * KVST)   // 89088
#define SMEM_ATTN (ASM_SMALL + 64 * 4 + 128 * 4 + 32 * 4)

__global__ __launch_bounds__(128) void attn_mma() {
    extern __shared__ char smb[];
    const uint32_t sb = smem_u32(smb);
    float* lsum  = (float*)(smb + ASM_SMALL);
    float* vcorr = lsum + 64;
    int*   slist = (int*)(vcorr + 128);

    const int qb = blockIdx.x, h = blockIdx.y;
    const int tid = threadIdx.x, wm = tid >> 5, lane = tid & 31;
    const int lrow = lane & 15, lcb = (lane >> 4) << 4;

    const int cnt = g_cnt[h * NQB + qb];
    if (tid < 32) slist[tid] = g_list[(h * NQB + qb) * NKB + tid];

    {
        const size_t gq = ((size_t)h * S + qb * 64) * HD;
#pragma unroll
        for (int u = 0; u < 8; u++) {
            const int idx = tid + 128 * u;
            const int r = idx >> 4, c = idx & 15;
            CP_ASYNC16(sb + AQ + r * QSTR + c * 16, (const char*)&g_Qh[gq + (size_t)r * HD + c * 8]);
        }
        CP_COMMIT();
    }
    __syncthreads();

#define ISSUE_KV(ii, buf) do {                                                      \
    const int kb_ = slist[ii];                                                      \
    const size_t gk_ = ((size_t)h * S + kb_ * 64) * HD;                             \
    const size_t gv_ = (size_t)h * HD * S + (size_t)kb_ * 64;                       \
    _Pragma("unroll")                                                               \
    for (int u = 0; u < 8; u++) {                                                   \
        const int idx = tid + 128 * u;                                              \
        const int r = idx >> 4, c = idx & 15;                                       \
        CP_ASYNC16(sb + AK(buf) + r * QSTR + c * 16, (const char*)&g_Kh[gk_ + (size_t)r * HD + c * 8]); \
        const int rv = idx >> 3, cv = idx & 7;                                      \
        CP_ASYNC16(sb + AV(buf) + rv * VSTR + cv * 16, (const char*)&g_Vth[gv_ + (size_t)rv * S + cv * 8]); \
    }                                                                               \
    CP_COMMIT();                                                                    \
} while (0)

    if (cnt > 0) ISSUE_KV(0, 0);

    {
        const int* mrow = &g_mask[(h * NQB + qb) * NKB];
        float vc = 0.f;
        for (int kb = 0; kb < NKB; kb++)
            if (!mrow[kb]) vc += g_Vblk[((size_t)h * NKB + kb) * HD + tid];
        vcorr[tid] = vc * EXPC;
        if (tid < 64) lsum[tid] = (float)(S - 64 * cnt) * EXPC;
    }
    __syncthreads();

    float oacc[16][4];
#pragma unroll
    for (int i = 0; i < 16; i++)
#pragma unroll
        for (int e = 0; e < 4; e++) oacc[i][e] = 0.f;

    for (int ii = 0; ii < cnt; ii++) {
        const int buf = ii & 1;
        if (ii + 1 < cnt) {
            ISSUE_KV(ii + 1, buf ^ 1);
            asm volatile("cp.async.wait_group 1;" ::: "memory");
        } else {
            asm volatile("cp.async.wait_group 0;" ::: "memory");
        }
        __syncthreads();

        float sacc[8][4];
#pragma unroll
        for (int i = 0; i < 8; i++)
#pragma unroll
            for (int e = 0; e < 4; e++) sacc[i][e] = 0.f;
#pragma unroll
        for (int kt = 0; kt < 8; kt++) {
            uint32_t qh[4];
            ldsm4(qh, sb + AQ + (wm * 16 + lrow) * QSTR + kt * 32 + lcb);
#pragma unroll
            for (int jt = 0; jt < 4; jt++) {
                uint32_t kh[4];
                ldsm4(kh, sb + AK(buf) + (jt * 16 + lrow) * QSTR + kt * 32 + lcb);
                mma_f16(sacc[2 * jt],     qh, kh[0], kh[2]);
                mma_f16(sacc[2 * jt + 1], qh, kh[1], kh[3]);
            }
        }

        uint32_t pah[4][4];
        float rs0 = 0.f, rs1 = 0.f;
#pragma unroll
        for (int nt = 0; nt < 8; nt++) {
            const float p0 = __expf(fmaf(sacc[nt][0], SCALE, -ESHIFT));
            const float p1 = __expf(fmaf(sacc[nt][1], SCALE, -ESHIFT));
            const float p2 = __expf(fmaf(sacc[nt][2], SCALE, -ESHIFT));
            const float p3 = __expf(fmaf(sacc[nt][3], SCALE, -ESHIFT));
            rs0 += p0 + p1;
            rs1 += p2 + p3;
            const int g = nt >> 1, o = (nt & 1) * 2;
            pah[g][o]     = packh2(p0, p1);
            pah[g][o + 1] = packh2(p2, p3);
        }
        rs0 += __shfl_xor_sync(0xffffffffu, rs0, 1);
        rs0 += __shfl_xor_sync(0xffffffffu, rs0, 2);
        rs1 += __shfl_xor_sync(0xffffffffu, rs1, 1);
        rs1 += __shfl_xor_sync(0xffffffffu, rs1, 2);
        if ((lane & 3) == 0) {
            lsum[wm * 16 + (lane >> 2)]     += rs0;
            lsum[wm * 16 + (lane >> 2) + 8] += rs1;
        }

#pragma unroll
        for (int g = 0; g < 4; g++) {
#pragma unroll
            for (int dt = 0; dt < 8; dt++) {
                uint32_t vh[4];
                ldsm4(vh, sb + AV(buf) + (dt * 16 + lrow) * VSTR + g * 32 + lcb);
                mma_f16(oacc[2 * dt],     pah[g], vh[0], vh[2]);
                mma_f16(oacc[2 * dt + 1], pah[g], vh[1], vh[3]);
            }
        }
        __syncthreads();
    }
    asm volatile("cp.async.wait_group 0;" ::: "memory");
    __syncthreads();

    const int r0 = wm * 16 + (lane >> 2);
    const float il0 = 1.f / lsum[r0];
    const float il1 = 1.f / lsum[r0 + 8];
    const int cbase = 2 * (lane & 3);
    const size_t ob0 = (size_t)(qb * 64 + r0) * HID + h * HD;
    const size_t ob1 = ob0 + (size_t)8 * HID;
#pragma unroll
    for (int ot = 0; ot < 16; ot++) {
        const int c = 8 * ot + cbase;
        const float a0 = (oacc[ot][0] + vcorr[c]) * il0;
        const float a1 = (oacc[ot][1] + vcorr[c + 1]) * il0;
        const float b0 = (oacc[ot][2] + vcorr[c]) * il1;
        const float b1 = (oacc[ot][3] + vcorr[c + 1]) * il1;
        ((uint32_t*)g_ATh)[(ob0 + c) >> 1] = packh2(a0, a1);
        ((uint32_t*)g_ATh)[(ob1 + c) >> 1] = packh2(b0, b1);
    }
}

// ---------------------------------------------------------------------------
extern "C" void kernel_launch(void* const* d_in, const int* in_sizes, int n_in,
                              void* d_out, int out_size) {
    const float* X  = (const float*)d_in[0];
    const float* qw = (const float*)d_in[1];
    const float* kw = (const float*)d_in[2];
    const float* vw = (const float*)d_in[3];
    const float* ow = (const float*)d_in[4];
    const float* sp = (const float*)d_in[5];
    float* out = (float*)d_out;

    cudaFuncSetAttribute(mma_gemm, cudaFuncAttributeMaxDynamicSharedMemorySize, GEMM_SMEM);
    cudaFuncSetAttribute(attn_mma, cudaFuncAttributeMaxDynamicSharedMemorySize, SMEM_ATTN);

    convert_h<<<(S * HID / 4 + 255) / 256, 256>>>(X);            // 0
    convert_T4<<<dim3(64, 64, 4), dim3(32, 8)>>>(qw, kw, vw, ow);// 1
    mask_kernel<<<dim3(NH, 4), 256>>>(sp);                       // 2
    mma_gemm<<<dim3(16, 16, 3), 128, GEMM_SMEM>>>(nullptr, -1);  // 3 <- ncu window
    attn_mma<<<dim3(NQB, NH), 128, SMEM_ATTN>>>();               // 4
    mma_gemm<<<dim3(16, 16), 128, GEMM_SMEM>>>(out, 3);          // 5
}

// round 17
// speedup vs baseline: 2.6167x; 1.0023x over previous
#include <cuda_runtime.h>
#include <cuda_fp16.h>
#include <math.h>
#include <stdint.h>

// Problem constants
#define S     2048
#define HID   2048
#define NH    16
#define HD    128
#define BS_   64
#define NQB   32
#define NKB   32
#define KSEL  511
#define SCALE 0.08838834764831845f
#define ESHIFT 4.0f
#define EXPC  0.01831563889f   // e^-4

// ---------------- device scratch (allocation-free) ----------------
__device__ float g_Vblk[NH * NKB * HD];
__device__ int   g_mask[NH * NQB * NKB];
__device__ int   g_list[NH * NQB * NKB];
__device__ int   g_cnt[NH * NQB];

// plain fp16 operands everywhere
__device__ __half g_Xh[S * HID];
__device__ __half g_Wh[4][HID * HID];
__device__ __half g_ATh[S * HID];

__device__ __half g_Qh[NH * S * HD];
__device__ __half g_Kh[NH * S * HD];
__device__ __half g_Vth[NH * HD * S];    // [h][d][s]

// ---------------- helpers ----------------
__device__ __forceinline__ uint32_t smem_u32(const void* p) {
    uint32_t a;
    asm("{ .reg .u64 t; cvta.to.shared.u64 t, %1; cvt.u32.u64 %0, t; }" : "=r"(a) : "l"(p));
    return a;
}
__device__ __forceinline__ void ldsm4(uint32_t (&r)[4], uint32_t addr) {
    asm volatile("ldmatrix.sync.aligned.m8n8.x4.shared.b16 {%0,%1,%2,%3}, [%4];"
        : "=r"(r[0]), "=r"(r[1]), "=r"(r[2]), "=r"(r[3]) : "r"(addr));
}
__device__ __forceinline__ void mma_f16(float (&d)[4], const uint32_t (&a)[4],
                                        uint32_t b0, uint32_t b1) {
    asm volatile("mma.sync.aligned.m16n8k16.row.col.f32.f16.f16.f32 "
        "{%0,%1,%2,%3}, {%4,%5,%6,%7}, {%8,%9}, {%0,%1,%2,%3};"
        : "+f"(d[0]), "+f"(d[1]), "+f"(d[2]), "+f"(d[3])
        : "r"(a[0]), "r"(a[1]), "r"(a[2]), "r"(a[3]), "r"(b0), "r"(b1));
}
#define CP_ASYNC16(dst, src) \
    asm volatile("cp.async.cg.shared.global [%0], [%1], 16;" :: "r"(dst), "l"(src))
#define CP_COMMIT() asm volatile("cp.async.commit_group;" ::: "memory")

__device__ __forceinline__ uint32_t packh2(float a, float b) {
    __half2 h = __floats2half2_rn(a, b);
    return *reinterpret_cast<uint32_t*>(&h);
}

// ---------------- conversions ----------------
__global__ void convert_h(const float* __restrict__ src) {
    int i = blockIdx.x * blockDim.x + threadIdx.x;
    float4 v = ((const float4*)src)[i];
    ushort4 hv = { __half_as_ushort(__float2half_rn(v.x)),
                   __half_as_ushort(__float2half_rn(v.y)),
                   __half_as_ushort(__float2half_rn(v.z)),
                   __half_as_ushort(__float2half_rn(v.w)) };
    ((ushort4*)g_Xh)[i] = hv;
}

__global__ void convert_T4(const float* __restrict__ qw, const float* __restrict__ kw,
                           const float* __restrict__ vw, const float* __restrict__ ow) {
    __shared__ float t[32][33];
    const int widx = blockIdx.z;
    const float* W = (widx == 0) ? qw : (widx == 1) ? kw : (widx == 2) ? vw : ow;
    const int k0 = blockIdx.y * 32, n0 = blockIdx.x * 32;
    const int tx = threadIdx.x, ty = threadIdx.y;
#pragma unroll
    for (int j = 0; j < 4; j++)
        t[ty + 8 * j][tx] = W[(size_t)(k0 + ty + 8 * j) * HID + n0 + tx];
    __syncthreads();
#pragma unroll
    for (int j = 0; j < 4; j++) {
        const int n = n0 + ty + 8 * j, k = k0 + tx;
        g_Wh[widx][(size_t)n * HID + k] = __float2half_rn(t[tx][ty + 8 * j]);
    }
}

// ---------------- mask (parallel count) + fused list build ----------------
__global__ void mask_kernel(const float* __restrict__ sp) {
    __shared__ float v[1024];
    __shared__ int msk[256];
    const int h = blockIdx.x, chunk = blockIdx.y, t = threadIdx.x;  // 256 thr
    for (int i = t; i < 1024; i += 256) v[i] = sp[h * 1024 + i];
    __syncthreads();
    const int idx = chunk * 256 + t;
    const float mine = v[idx];
    int c = 0;
#pragma unroll 8
    for (int i = 0; i < 1024; i++) c += (v[i] >= mine);
    const int sel = (c <= KSEL) ? 1 : 0;
    g_mask[h * 1024 + idx] = sel;
    msk[t] = sel;
    __syncthreads();
    if (t < 8) {
        const int qb = chunk * 8 + t;
        int cc = 0;
        for (int kb = 0; kb < NKB; kb++)
            if (msk[t * 32 + kb]) g_list[(h * NQB + qb) * NKB + cc++] = kb;
        g_cnt[h * NQB + qb] = cc;
    }
}

// ---------------- mma.sync fp16 GEMM: 128 thr, 4 warps @ 64x64, 3-stage ----------------
#define SROW    80
#define TILE_SM (128 * SROW)        // 10240
#define STAGE   (2 * TILE_SM)       // 20480 (A + B)
#define GEMM_SMEM 67584             // ring 3*20480=61440; epilogue 128*132*4

__global__ __launch_bounds__(128, 3) void mma_gemm(float* __restrict__ Cext, int modeArg) {
    extern __shared__ char sm8[];
    const uint32_t sb = smem_u32(sm8);
    const int tid = threadIdx.x, wid = tid >> 5, lane = tid & 31;
    const int m0 = blockIdx.y * 128, n0 = blockIdx.x * 128;
    const int wm = wid & 1, wn = wid >> 1;        // 2 x 2 warp grid, 64x64 each
    const int mode = (modeArg < 0) ? (int)blockIdx.z : modeArg;

    const __half* Ah = (mode == 3) ? g_ATh : g_Xh;
    const __half* Bh = g_Wh[mode];

    float acc[4][8][4];
#pragma unroll
    for (int mt = 0; mt < 4; mt++)
#pragma unroll
        for (int nt = 0; nt < 8; nt++)
#pragma unroll
            for (int e = 0; e < 4; e++) acc[mt][nt][e] = 0.f;

#define ISSUE(cc, buf) do {                                                        \
    const int k0_ = (cc) * 32;                                                     \
    const uint32_t s0_ = sb + (buf) * STAGE;                                       \
    _Pragma("unroll")                                                              \
    for (int u = 0; u < 4; u++) {                                                  \
        const int idx = tid + 128 * u;                                             \
        const int r = idx >> 2, c16 = idx & 3;                                     \
        const uint32_t doff = r * SROW + c16 * 16;                                 \
        CP_ASYNC16(s0_ + doff,           (const char*)&Ah[(size_t)(m0 + r) * HID + k0_ + c16 * 8]); \
        CP_ASYNC16(s0_ + TILE_SM + doff, (const char*)&Bh[(size_t)(n0 + r) * HID + k0_ + c16 * 8]); \
    }                                                                              \
    CP_COMMIT();                                                                   \
} while (0)

    // 3-stage ring, ONE sync per chunk. Order: wait -> sync -> issue(c+2) -> compute(c).
    // Buffer (c+2)%3 == (c-1)%3 was last read in compute(c-1), which all threads
    // finished before this iteration's barrier.
    ISSUE(0, 0);
    ISSUE(1, 1);
    for (int c = 0; c < 64; c++) {
        if (c < 62) {
            asm volatile("cp.async.wait_group 1;" ::: "memory");
        } else {
            asm volatile("cp.async.wait_group 0;" ::: "memory");
        }
        __syncthreads();
        if (c < 62) ISSUE(c + 2, (c + 2) % 3);

        const uint32_t s0 = sb + (c % 3) * STAGE;
        const int kb2 = ((lane >> 4) * 8) * 2;
        const int ar = wm * 64 + (lane & 15);
        const int br = wn * 64 + (lane & 15);
#pragma unroll
        for (int ks = 0; ks < 2; ks++) {
            const int kbyte = ks * 32 + kb2;
            uint32_t ah[4][4];
#pragma unroll
            for (int mt = 0; mt < 4; mt++)
                ldsm4(ah[mt], s0 + (ar + mt * 16) * SROW + kbyte);
            uint32_t bh[4][4];
#pragma unroll
            for (int bt = 0; bt < 4; bt++)
                ldsm4(bh[bt], s0 + TILE_SM + (br + bt * 16) * SROW + kbyte);
#pragma unroll
            for (int mt = 0; mt < 4; mt++)
#pragma unroll
                for (int nt = 0; nt < 8; nt++) {
                    const int bt = nt >> 1, sel = nt & 1;
                    mma_f16(acc[mt][nt], ah[mt], bh[bt][sel], bh[bt][sel + 2]);
                }
        }
    }
    __syncthreads();

    // ---- epilogue via smem tile ----
    float* Cs = (float*)sm8;   // 128 x 132
#pragma unroll
    for (int mt = 0; mt < 4; mt++)
#pragma unroll
        for (int nt = 0; nt < 8; nt++) {
            const int r = wm * 64 + mt * 16 + (lane >> 2);
            const int col = wn * 64 + nt * 8 + (lane & 3) * 2;
            Cs[r * 132 + col]           = acc[mt][nt][0];
            Cs[r * 132 + col + 1]       = acc[mt][nt][1];
            Cs[(r + 8) * 132 + col]     = acc[mt][nt][2];
            Cs[(r + 8) * 132 + col + 1] = acc[mt][nt][3];
        }
    __syncthreads();

    const int h = blockIdx.x;
    if (mode <= 1) {
        __half* G = mode ? g_Kh : g_Qh;
        for (int p = tid; p < 128 * 64; p += 128) {
            const int r = p >> 6, d = p & 63;
            const float v1 = Cs[r * 132 + d];
            const float v2 = Cs[r * 132 + d + 64];
            const int s_ = m0 + r;
            const float invf = expf(-0.14391156831212788f * (float)d);
            const float ang = (float)s_ * invf;
            float sn, cs;
            sincosf(ang, &sn, &cs);
            const size_t base = ((size_t)h * S + s_) * HD;
            G[base + d]      = __float2half_rn(v1 * cs - v2 * sn);
            G[base + d + 64] = __float2half_rn(v2 * cs + v1 * sn);
        }
    } else if (mode == 2) {
        const int d = tid;   // 0..127
#pragma unroll
        for (int seg = 0; seg < 2; seg++) {
            const size_t base = ((size_t)h * HD + d) * S + m0 + seg * 64;
            float bsum = 0.f;
#pragma unroll
            for (int rr = 0; rr < 16; rr++) {
                const float v0 = Cs[(seg * 64 + rr * 4 + 0) * 132 + d];
                const float v1 = Cs[(seg * 64 + rr * 4 + 1) * 132 + d];
                const float v2 = Cs[(seg * 64 + rr * 4 + 2) * 132 + d];
                const float v3 = Cs[(seg * 64 + rr * 4 + 3) * 132 + d];
                bsum += v0 + v1 + v2 + v3;
                ushort4 hv;
                hv.x = __half_as_ushort(__float2half_rn(v0));
                hv.y = __half_as_ushort(__float2half_rn(v1));
                hv.z = __half_as_ushort(__float2half_rn(v2));
                hv.w = __half_as_ushort(__float2half_rn(v3));
                *(ushort4*)&g_Vth[base + rr * 4] = hv;
            }
            const int kb = blockIdx.y * 2 + seg;
            g_Vblk[((size_t)h * NKB + kb) * HD + d] = bsum;
        }
    } else {
        for (int p = tid; p < 128 * 32; p += 128) {
            const int r = p >> 5, c4 = p & 31;
            float4 v = *(float4*)&Cs[r * 132 + c4 * 4];
            *(float4*)&Cext[(size_t)(m0 + r) * HID + n0 + c4 * 4] = v;
        }
    }
}

// ---------------- mma.sync block-sparse attention (fp16 1-chain, K/V double buffered) ----------------
#define QSTR 272
#define VSTR 144
#define AQ   0
#define KVST 35840
#define AK(b) (17408 + (b) * KVST)
#define AV(b) (AK(b) + 17408)
#define ASM_SMALL (17408 + 2 * KVST)   // 89088
#define SMEM_ATTN (ASM_SMALL + 64 * 4 + 128 * 4 + 32 * 4)

__global__ __launch_bounds__(128) void attn_mma() {
    extern __shared__ char smb[];
    const uint32_t sb = smem_u32(smb);
    float* lsum  = (float*)(smb + ASM_SMALL);
    float* vcorr = lsum + 64;
    int*   slist = (int*)(vcorr + 128);

    const int qb = blockIdx.x, h = blockIdx.y;
    const int tid = threadIdx.x, wm = tid >> 5, lane = tid & 31;
    const int lrow = lane & 15, lcb = (lane >> 4) << 4;

    const int cnt = g_cnt[h * NQB + qb];
    if (tid < 32) slist[tid] = g_list[(h * NQB + qb) * NKB + tid];

    {
        const size_t gq = ((size_t)h * S + qb * 64) * HD;
#pragma unroll
        for (int u = 0; u < 8; u++) {
            const int idx = tid + 128 * u;
            const int r = idx >> 4, c = idx & 15;
            CP_ASYNC16(sb + AQ + r * QSTR + c * 16, (const char*)&g_Qh[gq + (size_t)r * HD + c * 8]);
        }
        CP_COMMIT();
    }
    __syncthreads();

#define ISSUE_KV(ii, buf) do {                                                      \
    const int kb_ = slist[ii];                                                      \
    const size_t gk_ = ((size_t)h * S + kb_ * 64) * HD;                             \
    const size_t gv_ = (size_t)h * HD * S + (size_t)kb_ * 64;                       \
    _Pragma("unroll")                                                               \
    for (int u = 0; u < 8; u++) {                                                   \
        const int idx = tid + 128 * u;                                              \
        const int r = idx >> 4, c = idx & 15;                                       \
        CP_ASYNC16(sb + AK(buf) + r * QSTR + c * 16, (const char*)&g_Kh[gk_ + (size_t)r * HD + c * 8]); \
        const int rv = idx >> 3, cv = idx & 7;                                      \
        CP_ASYNC16(sb + AV(buf) + rv * VSTR + cv * 16, (const char*)&g_Vth[gv_ + (size_t)rv * S + cv * 8]); \
    }                                                                               \
    CP_COMMIT();                                                                    \
} while (0)

    if (cnt > 0) ISSUE_KV(0, 0);

    {
        const int* mrow = &g_mask[(h * NQB + qb) * NKB];
        float vc = 0.f;
        for (int kb = 0; kb < NKB; kb++)
            if (!mrow[kb]) vc += g_Vblk[((size_t)h * NKB + kb) * HD + tid];
        vcorr[tid] = vc * EXPC;
        if (tid < 64) lsum[tid] = (float)(S - 64 * cnt) * EXPC;
    }
    __syncthreads();

    float oacc[16][4];
#pragma unroll
    for (int i = 0; i < 16; i++)
#pragma unroll
        for (int e = 0; e < 4; e++) oacc[i][e] = 0.f;

    for (int ii = 0; ii < cnt; ii++) {
        const int buf = ii & 1;
        if (ii + 1 < cnt) {
            ISSUE_KV(ii + 1, buf ^ 1);
            asm volatile("cp.async.wait_group 1;" ::: "memory");
        } else {
            asm volatile("cp.async.wait_group 0;" ::: "memory");
        }
        __syncthreads();

        float sacc[8][4];
#pragma unroll
        for (int i = 0; i < 8; i++)
#pragma unroll
            for (int e = 0; e < 4; e++) sacc[i][e] = 0.f;
#pragma unroll
        for (int kt = 0; kt < 8; kt++) {
            uint32_t qh[4];
            ldsm4(qh, sb + AQ + (wm * 16 + lrow) * QSTR + kt * 32 + lcb);
#pragma unroll
            for (int jt = 0; jt < 4; jt++) {
                uint32_t kh[4];
                ldsm4(kh, sb + AK(buf) + (jt * 16 + lrow) * QSTR + kt * 32 + lcb);
                mma_f16(sacc[2 * jt],     qh, kh[0], kh[2]);
                mma_f16(sacc[2 * jt + 1], qh, kh[1], kh[3]);
            }
        }

        uint32_t pah[4][4];
        float rs0 = 0.f, rs1 = 0.f;
#pragma unroll
        for (int nt = 0; nt < 8; nt++) {
            const float p0 = __expf(fmaf(sacc[nt][0], SCALE, -ESHIFT));
            const float p1 = __expf(fmaf(sacc[nt][1], SCALE, -ESHIFT));
            const float p2 = __expf(fmaf(sacc[nt][2], SCALE, -ESHIFT));
            const float p3 = __expf(fmaf(sacc[nt][3], SCALE, -ESHIFT));
            rs0 += p0 + p1;
            rs1 += p2 + p3;
            const int g = nt >> 1, o = (nt & 1) * 2;
            pah[g][o]     = packh2(p0, p1);
            pah[g][o + 1] = packh2(p2, p3);
        }
        rs0 += __shfl_xor_sync(0xffffffffu, rs0, 1);
        rs0 += __shfl_xor_sync(0xffffffffu, rs0, 2);
        rs1 += __shfl_xor_sync(0xffffffffu, rs1, 1);
        rs1 += __shfl_xor_sync(0xffffffffu, rs1, 2);
        if ((lane & 3) == 0) {
            lsum[wm * 16 + (lane >> 2)]     += rs0;
            lsum[wm * 16 + (lane >> 2) + 8] += rs1;
        }

#pragma unroll
        for (int g = 0; g < 4; g++) {
#pragma unroll
            for (int dt = 0; dt < 8; dt++) {
                uint32_t vh[4];
                ldsm4(vh, sb + AV(buf) + (dt * 16 + lrow) * VSTR + g * 32 + lcb);
                mma_f16(oacc[2 * dt],     pah[g], vh[0], vh[2]);
                mma_f16(oacc[2 * dt + 1], pah[g], vh[1], vh[3]);
            }
        }
        __syncthreads();
    }
    asm volatile("cp.async.wait_group 0;" ::: "memory");
    __syncthreads();

    const int r0 = wm * 16 + (lane >> 2);
    const float il0 = 1.f / lsum[r0];
    const float il1 = 1.f / lsum[r0 + 8];
    const int cbase = 2 * (lane & 3);
    const size_t ob0 = (size_t)(qb * 64 + r0) * HID + h * HD;
    const size_t ob1 = ob0 + (size_t)8 * HID;
#pragma unroll
    for (int ot = 0; ot < 16; ot++) {
        const int c = 8 * ot + cbase;
        const float a0 = (oacc[ot][0] + vcorr[c]) * il0;
        const float a1 = (oacc[ot][1] + vcorr[c + 1]) * il0;
        const float b0 = (oacc[ot][2] + vcorr[c]) * il1;
        const float b1 = (oacc[ot][3] + vcorr[c + 1]) * il1;
        ((uint32_t*)g_ATh)[(ob0 + c) >> 1] = packh2(a0, a1);
        ((uint32_t*)g_ATh)[(ob1 + c) >> 1] = packh2(b0, b1);
    }
}

// ---------------------------------------------------------------------------
extern "C" void kernel_launch(void* const* d_in, const int* in_sizes, int n_in,
                              void* d_out, int out_size) {
    const float* X  = (const float*)d_in[0];
    const float* qw = (const float*)d_in[1];
    const float* kw = (const float*)d_in[2];
    const float* vw = (const float*)d_in[3];
    const float* ow = (const float*)d_in[4];
    const float* sp = (const float*)d_in[5];
    float* out = (float*)d_out;

    cudaFuncSetAttribute(mma_gemm, cudaFuncAttributeMaxDynamicSharedMemorySize, GEMM_SMEM);
    cudaFuncSetAttribute(attn_mma, cudaFuncAttributeMaxDynamicSharedMemorySize, SMEM_ATTN);

    convert_h<<<(S * HID / 4 + 255) / 256, 256>>>(X);            // 0
    convert_T4<<<dim3(64, 64, 4), dim3(32, 8)>>>(qw, kw, vw, ow);// 1
    mask_kernel<<<dim3(NH, 4), 256>>>(sp);                       // 2
    mma_gemm<<<dim3(16, 16, 3), 128, GEMM_SMEM>>>(nullptr, -1);  // 3 <- ncu window
    attn_mma<<<dim3(NQB, NH), 128, SMEM_ATTN>>>();               // 4
    mma_gemm<<<dim3(16, 16), 128, GEMM_SMEM>>>(out, 3);          // 5
}